// round 8
// baseline (speedup 1.0000x reference)
#include <cuda_runtime.h>
#include <cuda_fp16.h>
#include <cstdint>

#define BSZ 8192
#define CDIM 128
#define DDIM 256
#define TILE 128
#define NTILE 64          // BSZ / TILE
#define NPAIRS 2080       // NTILE*(NTILE+1)/2

// ---------------- scratch (static device globals; no allocation) ----------------
__device__ unsigned g_se[(size_t)BSZ * BSZ];    // packed (sim fp16 | eud fp16); upper tiles only
__device__ __half g_lab_h[(size_t)BSZ * CDIM];  // pre-normalized labels, fp16
__device__ __half g_out_h[(size_t)BSZ * DDIM];  // outputs, fp16
__device__ float g_sq[BSZ];                     // ||fp16(output_i)||^2 (fp32 accum)
__device__ float2 g_part[(size_t)BSZ * NTILE];  // per-(row, tile) partial (pos, neg) sums
__device__ float g_rowloss[BSZ];
__device__ unsigned g_smin_enc, g_smax_enc, g_emax_enc;

// monotone float <-> uint encoding so min/max reduce with integer atomics
__device__ __forceinline__ unsigned fenc(float f) {
    unsigned u = __float_as_uint(f);
    return (u & 0x80000000u) ? ~u : (u | 0x80000000u);
}
__device__ __forceinline__ float fdec(unsigned e) {
    unsigned u = (e & 0x80000000u) ? (e & 0x7FFFFFFFu) : ~e;
    return __uint_as_float(u);
}

// triangular pair decode: k in [0, NPAIRS) -> (a, b) with 0 <= a <= b < NTILE
__device__ __forceinline__ int tri_off(int a) { return a * NTILE - (a * (a - 1)) / 2; }
__device__ __forceinline__ void tri_decode(int k, int& a, int& b) {
    int aa = (int)((129.0f - sqrtf(16641.0f - 8.0f * (float)k)) * 0.5f);
    aa = max(0, min(63, aa));
    while (aa < 63 && tri_off(aa + 1) <= k) aa++;
    while (aa > 0 && tri_off(aa) > k) aa--;
    a = aa;
    b = aa + (k - tri_off(aa));
}

__device__ __forceinline__ uint32_t smem_u32(const void* p) {
    uint32_t a;
    asm("{ .reg .u64 t; cvta.to.shared.u64 t, %1; cvt.u32.u64 %0, t; }" : "=r"(a) : "l"(p));
    return a;
}
__device__ __forceinline__ uint4 ldsm_x4(uint32_t addr) {
    uint4 r;
    asm volatile("ldmatrix.sync.aligned.m8n8.x4.shared.b16 {%0,%1,%2,%3}, [%4];"
                 : "=r"(r.x), "=r"(r.y), "=r"(r.z), "=r"(r.w) : "r"(addr));
    return r;
}
__device__ __forceinline__ void mma16(float* c, uint4 a, uint32_t b0, uint32_t b1) {
    asm volatile(
        "mma.sync.aligned.m16n8k16.row.col.f32.f16.f16.f32 "
        "{%0,%1,%2,%3}, {%4,%5,%6,%7}, {%8,%9}, {%0,%1,%2,%3};"
        : "+f"(c[0]), "+f"(c[1]), "+f"(c[2]), "+f"(c[3])
        : "r"(a.x), "r"(a.y), "r"(a.z), "r"(a.w), "r"(b0), "r"(b1));
}
__device__ __forceinline__ float ex2f(float x) {
    float y;
    asm("ex2.approx.f32 %0, %1;" : "=f"(y) : "f"(x));
    return y;
}
__device__ __forceinline__ float sqrtaf(float x) {
    float y;
    asm("sqrt.approx.f32 %0, %1;" : "=f"(y) : "f"(x));
    return y;
}
#define CP_ASYNC16(dst, src) \
    asm volatile("cp.async.cg.shared.global [%0], [%1], 16;" :: "r"(dst), "l"(src))
#define CP_COMMIT() asm volatile("cp.async.commit_group;" ::: "memory")
#define CP_WAIT0()  asm volatile("cp.async.wait_group 0;" ::: "memory")

// ---------------- gram smem layout (bytes) ----------------
#define OFF_STASH 65536
#define OFF_SQI   98304
#define OFF_SQJ   98816
#define SM_BYTES  99328

// copy one 128-row x 64-half tile into SW128-swizzled smem via cp.async
__device__ __forceinline__ void cpasync_tile(const __half* __restrict__ src, int ldh, int k0,
                                             uint32_t smem_dst, int tid) {
    #pragma unroll
    for (int it = 0; it < 4; it++) {
        int e = tid + 256 * it;                  // 0..1023 granules of 16B
        int row = e >> 3, gq = e & 7;
        const __half* g = src + (size_t)row * ldh + k0 + gq * 8;
        uint32_t bo = (uint32_t)(row * 128 + gq * 16);
        uint32_t dst = smem_dst + (bo ^ ((bo >> 3) & 0x70));
        CP_ASYNC16(dst, g);
    }
}

__device__ __forceinline__ unsigned pack_se(unsigned simlo16, float e) {
    unsigned eh = (unsigned)__half_as_ushort(__float2half_rn(e));
    return (simlo16 & 0xFFFFu) | (eh << 16);
}

// ---------------- kernel 0: reset global reduction scalars ----------------
__global__ void init_kernel() {
    g_smin_enc = fenc(3.4e38f);
    g_smax_enc = fenc(-3.4e38f);
    g_emax_enc = fenc(0.0f);
}

// ---------------- kernel 1: per-row prep (norms + fp16 conversion) ----------------
__global__ __launch_bounds__(128) void rowprep_kernel(const float* __restrict__ outputs,
                                                      const float* __restrict__ labels) {
    const int row = blockIdx.x;
    const int t = threadIdx.x;
    __shared__ float red[4];
    __shared__ float s_invn;

    float l = labels[(size_t)row * CDIM + t];
    float lsum = l * l;
    #pragma unroll
    for (int off = 16; off; off >>= 1) lsum += __shfl_xor_sync(0xffffffffu, lsum, off);
    if ((t & 31) == 0) red[t >> 5] = lsum;
    __syncthreads();
    if (t == 0) {
        float L = red[0] + red[1] + red[2] + red[3];
        s_invn = 1.0f / (sqrtf(L) + 1e-12f);
    }
    __syncthreads();
    g_lab_h[(size_t)row * CDIM + t] = __float2half(l * s_invn);

    float o0 = outputs[(size_t)row * DDIM + t];
    float o1 = outputs[(size_t)row * DDIM + 128 + t];
    __half h0 = __float2half(o0), h1 = __float2half(o1);
    g_out_h[(size_t)row * DDIM + t] = h0;
    g_out_h[(size_t)row * DDIM + 128 + t] = h1;
    float f0 = __half2float(h0), f1 = __half2float(h1);
    float osum = f0 * f0 + f1 * f1;
    #pragma unroll
    for (int off = 16; off; off >>= 1) osum += __shfl_xor_sync(0xffffffffu, osum, off);
    __syncthreads();
    if ((t & 31) == 0) red[t >> 5] = osum;
    __syncthreads();
    if (t == 0) g_sq[row] = red[0] + red[1] + red[2] + red[3];
}

// ---------------- kernel 2: fp16 mma fused grams, merged 6-chunk pipeline ----------------
__global__ __launch_bounds__(256, 2) void gram_mma() {
    int bi, bj;
    tri_decode(blockIdx.x, bi, bj);
    extern __shared__ float sm[];
    const uint32_t sb = smem_u32(sm);
    uint32_t* stash  = (uint32_t*)((char*)sm + OFF_STASH);  // thread-private sim tile
    float* s_sqi = (float*)((char*)sm + OFF_SQI);
    float* s_sqj = (float*)((char*)sm + OFF_SQJ);

    const int tid = threadIdx.x;
    const int wid = tid >> 5, lane = tid & 31;
    const int warp_m = wid >> 2, warp_n = wid & 3;
    const int g = lane >> 2, tig = lane & 3;
    const int i0 = bi * TILE, j0 = bj * TILE;

    if (tid < 128) {
        s_sqi[tid] = g_sq[i0 + tid];
        s_sqj[tid] = g_sq[j0 + tid];
    }

    // ldmatrix per-lane address precompute (byte offsets within 128x64h tile, 128B rows)
    const int laneA_row = lane & 15;
    const uint32_t baseA = (uint32_t)(((warp_m * 64 + laneA_row) << 7) + ((lane >> 4) << 4));
    const uint32_t xorA = (uint32_t)((laneA_row & 7) << 4);
    const int rowB = warp_n * 32 + ((lane >> 4) << 3) + (lane & 7);
    const uint32_t baseB = (uint32_t)((rowB << 7) + (((lane >> 3) & 1) << 4));
    const uint32_t xorB = (uint32_t)((rowB & 7) << 4);

    float c[4][4][4];
    #pragma unroll
    for (int mf = 0; mf < 4; mf++)
        #pragma unroll
        for (int nf = 0; nf < 4; nf++)
            #pragma unroll
            for (int r = 0; r < 4; r++) c[mf][nf][r] = 0.0f;

    const __half* AiL = g_lab_h + (size_t)i0 * CDIM;
    const __half* BjL = g_lab_h + (size_t)j0 * CDIM;
    const __half* AiO = g_out_h + (size_t)i0 * DDIM;
    const __half* BjO = g_out_h + (size_t)j0 * DDIM;

    // preload chunk 0 (labels, k0 = 0)
    cpasync_tile(AiL, CDIM, 0, sb, tid);
    cpasync_tile(BjL, CDIM, 0, sb + 16384, tid);
    CP_COMMIT();
    CP_WAIT0();
    __syncthreads();

    // merged pipeline: chunks 0-1 = label gram (K=128), chunks 2-5 = output gram (K=256)
    #pragma unroll 1
    for (int ch = 0; ch < 6; ch++) {
        if (ch < 5) {
            int nx = ch + 1;
            uint32_t nb = sb + (nx & 1) * 32768;
            if (nx < 2) {
                cpasync_tile(AiL, CDIM, nx * 64, nb, tid);
                cpasync_tile(BjL, CDIM, nx * 64, nb + 16384, tid);
            } else {
                cpasync_tile(AiO, DDIM, (nx - 2) * 64, nb, tid);
                cpasync_tile(BjO, DDIM, (nx - 2) * 64, nb + 16384, tid);
            }
            CP_COMMIT();
        }
        uint32_t sA = sb + (ch & 1) * 32768;
        uint32_t sB = sA + 16384;
        #pragma unroll
        for (int ks = 0; ks < 4; ks++) {
            uint4 a[4];
            #pragma unroll
            for (int mf = 0; mf < 4; mf++)
                a[mf] = ldsm_x4(sA + ((baseA + mf * 2048 + ks * 32) ^ xorA));
            uint4 b0 = ldsm_x4(sB + ((baseB + ks * 32) ^ xorB));
            uint4 b1 = ldsm_x4(sB + ((baseB + 2048 + ks * 32) ^ xorB));
            #pragma unroll
            for (int mf = 0; mf < 4; mf++) {
                mma16(c[mf][0], a[mf], b0.x, b0.y);
                mma16(c[mf][1], a[mf], b0.z, b0.w);
                mma16(c[mf][2], a[mf], b1.x, b1.y);
                mma16(c[mf][3], a[mf], b1.z, b1.w);
            }
        }
        if (ch == 1) {
            // epilogue A (overlaps chunk-2 cp.async): stash sim, min/max, zero accums
            float lmin = 3.4e38f, lmax = -3.4e38f;
            #pragma unroll
            for (int mf = 0; mf < 4; mf++) {
                #pragma unroll
                for (int nf = 0; nf < 4; nf++) {
                    float v0 = c[mf][nf][0], v1 = c[mf][nf][1];
                    float v2 = c[mf][nf][2], v3 = c[mf][nf][3];
                    lmin = fminf(lmin, fminf(fminf(v0, v1), fminf(v2, v3)));
                    lmax = fmaxf(lmax, fmaxf(fmaxf(v0, v1), fmaxf(v2, v3)));
                    int idx0 = (mf * 4 + nf) * 2;
                    __half2 h01 = __floats2half2_rn(v0, v1);
                    __half2 h23 = __floats2half2_rn(v2, v3);
                    stash[idx0 * 256 + tid]       = *(unsigned*)&h01;
                    stash[(idx0 + 1) * 256 + tid] = *(unsigned*)&h23;
                    c[mf][nf][0] = 0.0f; c[mf][nf][1] = 0.0f;
                    c[mf][nf][2] = 0.0f; c[mf][nf][3] = 0.0f;
                }
            }
            #pragma unroll
            for (int off = 16; off; off >>= 1) {
                lmin = fminf(lmin, __shfl_xor_sync(0xffffffffu, lmin, off));
                lmax = fmaxf(lmax, __shfl_xor_sync(0xffffffffu, lmax, off));
            }
            if (lane == 0) {
                atomicMin(&g_smin_enc, fenc(lmin));
                atomicMax(&g_smax_enc, fenc(lmax));
            }
        }
        if (ch < 5) {
            CP_WAIT0();
            __syncthreads();
        }
    }

    // epilogue B: eud + packed (sim|eud) store, upper tile only
    {
        float lemax = 0.0f;
        #pragma unroll
        for (int mf = 0; mf < 4; mf++) {
            int il = warp_m * 64 + mf * 16 + g;
            float q0 = s_sqi[il], q1 = s_sqi[il + 8];
            #pragma unroll
            for (int nf = 0; nf < 4; nf++) {
                int jl = warp_n * 32 + nf * 8 + 2 * tig;
                float r0 = s_sqj[jl], r1 = s_sqj[jl + 1];
                float d0 = q0 + r0 - 2.0f * c[mf][nf][0];
                float d1 = q0 + r1 - 2.0f * c[mf][nf][1];
                float d2_ = q1 + r0 - 2.0f * c[mf][nf][2];
                float d3 = q1 + r1 - 2.0f * c[mf][nf][3];
                float v0 = (d0 > 0.0f) ? sqrtaf(d0) : 0.0f;
                float v1 = (d1 > 0.0f) ? sqrtaf(d1) : 0.0f;
                float v2 = (d2_ > 0.0f) ? sqrtaf(d2_) : 0.0f;
                float v3 = (d3 > 0.0f) ? sqrtaf(d3) : 0.0f;
                if (i0 + il == j0 + jl) v0 = 0.0f;
                if (i0 + il == j0 + jl + 1) v1 = 0.0f;
                if (i0 + il + 8 == j0 + jl) v2 = 0.0f;
                if (i0 + il + 8 == j0 + jl + 1) v3 = 0.0f;
                lemax = fmaxf(lemax, fmaxf(fmaxf(v0, v1), fmaxf(v2, v3)));

                int idx0 = (mf * 4 + nf) * 2;
                unsigned sp01 = stash[idx0 * 256 + tid];
                unsigned sp23 = stash[(idx0 + 1) * 256 + tid];
                unsigned u0 = pack_se(sp01, v0);
                unsigned u1 = pack_se(sp01 >> 16, v1);
                unsigned u2 = pack_se(sp23, v2);
                unsigned u3 = pack_se(sp23 >> 16, v3);

                *(uint2*)&g_se[(size_t)(i0 + il) * BSZ + j0 + jl]     = make_uint2(u0, u1);
                *(uint2*)&g_se[(size_t)(i0 + il + 8) * BSZ + j0 + jl] = make_uint2(u2, u3);
            }
        }
        #pragma unroll
        for (int off = 16; off; off >>= 1)
            lemax = fmaxf(lemax, __shfl_xor_sync(0xffffffffu, lemax, off));
        if (lane == 0) atomicMax(&g_emax_enc, fenc(lemax));
    }
}

// ---------------- kernel 3: tile loss (reverse order for L2 reuse) ----------------
__global__ __launch_bounds__(256) void loss_tile_kernel() {
    int bi, bj;
    tri_decode(NPAIRS - 1 - (int)blockIdx.x, bi, bj);   // newest-written tiles first
    const int i0 = bi * TILE, j0 = bj * TILE;
    const int t = threadIdx.x;
    const int w = t >> 5, lane = t & 31;
    const int cg = lane & 15;        // 8-column group: cols cg*8 .. cg*8+7
    const int rhalf = lane >> 4;     // row within the pair

    const float L2E = 1.4426950408889634f;
    const float smin = fdec(g_smin_enc);
    const float smax = fdec(g_smax_enc);
    const float emax = fdec(g_emax_enc);
    const float c1 = L2E / (smax - smin);
    const float c0 = -smin * c1;
    const float c2 = L2E / emax;
    const float sthr = smin + 0.5f * (smax - smin);

    __shared__ float2 scol[8][128];

    float cp[8] = {0, 0, 0, 0, 0, 0, 0, 0};
    float cn[8] = {0, 0, 0, 0, 0, 0, 0, 0};

    #pragma unroll 1
    for (int it = 0; it < 8; it++) {
        const int row = w * 16 + it * 2 + rhalf;
        const uint4* base = (const uint4*)&g_se[(size_t)(i0 + row) * BSZ + j0 + cg * 8];
        uint4 v0 = base[0], v1 = base[1];
        unsigned uu[8] = {v0.x, v0.y, v0.z, v0.w, v1.x, v1.y, v1.z, v1.w};
        float rp = 0.0f, rn = 0.0f;
        #pragma unroll
        for (int x = 0; x < 8; x++) {
            float2 f = __half22float2(*(__half2*)&uu[x]);   // f.x = sim, f.y = eud
            float d = fmaf(f.y, c2, fmaf(f.x, c1, c0));
            bool pos = f.x > sthr;
            float val = ex2f(pos ? d : (L2E - d));
            float vp = pos ? val : 0.0f;
            float vn = pos ? 0.0f : val;
            rp += vp; rn += vn;
            cp[x] += vp; cn[x] += vn;
        }
        #pragma unroll
        for (int off = 8; off; off >>= 1) {
            rp += __shfl_xor_sync(0xffffffffu, rp, off);
            rn += __shfl_xor_sync(0xffffffffu, rn, off);
        }
        if (cg == 0)
            g_part[(size_t)(i0 + row) * NTILE + bj] = make_float2(rp, rn);
    }

    // fold the two row-halves' column partials, then cross-warp reduce in smem
    #pragma unroll
    for (int x = 0; x < 8; x++) {
        cp[x] += __shfl_xor_sync(0xffffffffu, cp[x], 16);
        cn[x] += __shfl_xor_sync(0xffffffffu, cn[x], 16);
    }
    if (rhalf == 0) {
        #pragma unroll
        for (int x = 0; x < 8; x++) scol[w][cg * 8 + x] = make_float2(cp[x], cn[x]);
    }
    __syncthreads();
    if (bi != bj && t < 128) {
        float p = 0.0f, n = 0.0f;
        #pragma unroll
        for (int ww = 0; ww < 8; ww++) {
            float2 v = scol[ww][t];
            p += v.x; n += v.y;
        }
        g_part[(size_t)(j0 + t) * NTILE + bi] = make_float2(p, n);
    }
}

// ---------------- kernel 4: per-row reduce of partials -> rowloss ----------------
__global__ __launch_bounds__(128) void rowreduce_kernel() {
    const int row = blockIdx.x * 128 + threadIdx.x;
    const float2* p = &g_part[(size_t)row * NTILE];
    float P = 0.0f, N = 0.0f;
    #pragma unroll
    for (int k = 0; k < NTILE; k++) {
        float2 v = p[k];
        P += v.x; N += v.y;
    }
    float lp = fmaxf(logf(P), 0.0f);   // log(0) = -inf -> clamped to 0
    float ln = fmaxf(logf(N), 0.0f);
    g_rowloss[row] = lp + ln;
}

// ---------------- kernel 5: deterministic final mean ----------------
__global__ __launch_bounds__(256) void final_kernel(float* __restrict__ out) {
    __shared__ float s[256];
    const int t = threadIdx.x;
    float a = 0.0f;
    for (int i = t; i < BSZ; i += 256) a += g_rowloss[i];
    s[t] = a;
    __syncthreads();
    #pragma unroll
    for (int o = 128; o; o >>= 1) {
        if (t < o) s[t] += s[t + o];
        __syncthreads();
    }
    if (t == 0) out[0] = s[0] * (1.0f / (float)BSZ);
}

// ---------------- launch ----------------
extern "C" void kernel_launch(void* const* d_in, const int* in_sizes, int n_in,
                              void* d_out, int out_size) {
    const float* outputs = (const float*)d_in[0];
    const float* labels  = (const float*)d_in[1];
    if (n_in >= 2 && in_sizes[0] == BSZ * CDIM && in_sizes[1] == BSZ * DDIM) {
        const float* tmp = outputs; outputs = labels; labels = tmp;
    }
    float* out = (float*)d_out;

    cudaFuncSetAttribute(gram_mma, cudaFuncAttributeMaxDynamicSharedMemorySize, SM_BYTES);

    init_kernel<<<1, 1>>>();
    rowprep_kernel<<<BSZ, 128>>>(outputs, labels);
    gram_mma<<<NPAIRS, 256, SM_BYTES>>>();
    loss_tile_kernel<<<NPAIRS, 256>>>();
    rowreduce_kernel<<<NTILE, 128>>>();
    final_kernel<<<1, 256>>>(out);
}

// round 10
// speedup vs baseline: 1.0141x; 1.0141x over previous
#include <cuda_runtime.h>
#include <cuda_fp16.h>
#include <cstdint>

#define BSZ 8192
#define CDIM 128
#define DDIM 256
#define TILE 128
#define NTILE 64          // BSZ / TILE
#define NPAIRS 2080       // NTILE*(NTILE+1)/2

// ---------------- scratch (static device globals; no allocation) ----------------
__device__ unsigned g_se[(size_t)BSZ * BSZ];    // packed (sim fp16 | eud fp16); upper tiles only
__device__ __half g_lab_h[(size_t)BSZ * CDIM];  // pre-normalized labels, fp16
__device__ __half g_out_h[(size_t)BSZ * DDIM];  // outputs, fp16
__device__ float g_sq[BSZ];                     // ||fp16(output_i)||^2 (fp32 accum)
__device__ float2 g_part[(size_t)BSZ * NTILE];  // per-(row, tile) partial (pos, neg) sums
__device__ float g_rowloss[BSZ];
__device__ unsigned g_smin_enc, g_smax_enc, g_emax_enc;

// monotone float <-> uint encoding so min/max reduce with integer atomics
__device__ __forceinline__ unsigned fenc(float f) {
    unsigned u = __float_as_uint(f);
    return (u & 0x80000000u) ? ~u : (u | 0x80000000u);
}
__device__ __forceinline__ float fdec(unsigned e) {
    unsigned u = (e & 0x80000000u) ? (e & 0x7FFFFFFFu) : ~e;
    return __uint_as_float(u);
}

// triangular pair decode: k in [0, NPAIRS) -> (a, b) with 0 <= a <= b < NTILE
__device__ __forceinline__ int tri_off(int a) { return a * NTILE - (a * (a - 1)) / 2; }
__device__ __forceinline__ void tri_decode(int k, int& a, int& b) {
    int aa = (int)((129.0f - sqrtf(16641.0f - 8.0f * (float)k)) * 0.5f);
    aa = max(0, min(63, aa));
    while (aa < 63 && tri_off(aa + 1) <= k) aa++;
    while (aa > 0 && tri_off(aa) > k) aa--;
    a = aa;
    b = aa + (k - tri_off(aa));
}

__device__ __forceinline__ uint32_t smem_u32(const void* p) {
    uint32_t a;
    asm("{ .reg .u64 t; cvta.to.shared.u64 t, %1; cvt.u32.u64 %0, t; }" : "=r"(a) : "l"(p));
    return a;
}
__device__ __forceinline__ uint4 ldsm_x4(uint32_t addr) {
    uint4 r;
    asm volatile("ldmatrix.sync.aligned.m8n8.x4.shared.b16 {%0,%1,%2,%3}, [%4];"
                 : "=r"(r.x), "=r"(r.y), "=r"(r.z), "=r"(r.w) : "r"(addr));
    return r;
}
__device__ __forceinline__ void mma16(float* c, uint4 a, uint32_t b0, uint32_t b1) {
    asm volatile(
        "mma.sync.aligned.m16n8k16.row.col.f32.f16.f16.f32 "
        "{%0,%1,%2,%3}, {%4,%5,%6,%7}, {%8,%9}, {%0,%1,%2,%3};"
        : "+f"(c[0]), "+f"(c[1]), "+f"(c[2]), "+f"(c[3])
        : "r"(a.x), "r"(a.y), "r"(a.z), "r"(a.w), "r"(b0), "r"(b1));
}
__device__ __forceinline__ float ex2f(float x) {
    float y;
    asm("ex2.approx.f32 %0, %1;" : "=f"(y) : "f"(x));
    return y;
}
__device__ __forceinline__ float sqrtaf(float x) {
    float y;
    asm("sqrt.approx.f32 %0, %1;" : "=f"(y) : "f"(x));
    return y;
}
__device__ __forceinline__ uint4 ldg_nc4(const void* p) {
    uint4 r;
    asm volatile("ld.global.nc.v4.u32 {%0,%1,%2,%3}, [%4];"
                 : "=r"(r.x), "=r"(r.y), "=r"(r.z), "=r"(r.w) : "l"(p));
    return r;
}
#define CP_ASYNC16(dst, src) \
    asm volatile("cp.async.cg.shared.global [%0], [%1], 16;" :: "r"(dst), "l"(src))
#define CP_COMMIT() asm volatile("cp.async.commit_group;" ::: "memory")
#define CP_WAIT(n)  asm volatile("cp.async.wait_group %0;" :: "n"(n) : "memory")

// ---------------- gram smem layout (bytes): 3 stages x 32KB + sq arrays ----------------
#define OFF_SQI   98304
#define OFF_SQJ   98816
#define SM_BYTES  99328

// copy one 128-row x 64-half tile into SW128-swizzled smem via cp.async
__device__ __forceinline__ void cpasync_tile(const __half* __restrict__ src, int ldh, int k0,
                                             uint32_t smem_dst, int tid) {
    #pragma unroll
    for (int it = 0; it < 4; it++) {
        int e = tid + 256 * it;                  // 0..1023 granules of 16B
        int row = e >> 3, gq = e & 7;
        const __half* g = src + (size_t)row * ldh + k0 + gq * 8;
        uint32_t bo = (uint32_t)(row * 128 + gq * 16);
        uint32_t dst = smem_dst + (bo ^ ((bo >> 3) & 0x70));
        CP_ASYNC16(dst, g);
    }
}

__device__ __forceinline__ unsigned pack_se(unsigned simlo16, float e) {
    unsigned eh = (unsigned)__half_as_ushort(__float2half_rn(e));
    return (simlo16 & 0xFFFFu) | (eh << 16);
}

// ---------------- kernel 0: reset global reduction scalars ----------------
__global__ void init_kernel() {
    g_smin_enc = fenc(3.4e38f);
    g_smax_enc = fenc(-3.4e38f);
    g_emax_enc = fenc(0.0f);
}

// ---------------- kernel 1: per-row prep, warp-per-row (no block syncs) ----------------
__global__ __launch_bounds__(256) void rowprep_kernel(const float* __restrict__ outputs,
                                                      const float* __restrict__ labels) {
    const int row = blockIdx.x * 8 + (threadIdx.x >> 5);
    const int lane = threadIdx.x & 31;

    // labels: 4 elements per lane
    float l[4];
    float lsum = 0.0f;
    #pragma unroll
    for (int x = 0; x < 4; x++) {
        l[x] = labels[(size_t)row * CDIM + lane + 32 * x];
        lsum += l[x] * l[x];
    }
    #pragma unroll
    for (int off = 16; off; off >>= 1) lsum += __shfl_xor_sync(0xffffffffu, lsum, off);
    float invn = 1.0f / (sqrtf(lsum) + 1e-12f);
    #pragma unroll
    for (int x = 0; x < 4; x++)
        g_lab_h[(size_t)row * CDIM + lane + 32 * x] = __float2half(l[x] * invn);

    // outputs: 8 elements per lane; sq from rounded values
    float osum = 0.0f;
    #pragma unroll
    for (int x = 0; x < 8; x++) {
        float o = outputs[(size_t)row * DDIM + lane + 32 * x];
        __half h = __float2half(o);
        g_out_h[(size_t)row * DDIM + lane + 32 * x] = h;
        float f = __half2float(h);
        osum += f * f;
    }
    #pragma unroll
    for (int off = 16; off; off >>= 1) osum += __shfl_xor_sync(0xffffffffu, osum, off);
    if (lane == 0) g_sq[row] = osum;
}

// ---------------- kernel 2: fp16 mma fused grams, race-free 3-stage pipeline ----------------
__global__ __launch_bounds__(256, 2) void gram_mma() {
    int bi, bj;
    tri_decode(blockIdx.x, bi, bj);
    extern __shared__ float sm[];
    const uint32_t sb = smem_u32(sm);
    float* s_sqi = (float*)((char*)sm + OFF_SQI);
    float* s_sqj = (float*)((char*)sm + OFF_SQJ);

    const int tid = threadIdx.x;
    const int wid = tid >> 5, lane = tid & 31;
    const int warp_m = wid >> 2, warp_n = wid & 3;
    const int g = lane >> 2, tig = lane & 3;
    const int i0 = bi * TILE, j0 = bj * TILE;

    if (tid < 128) {
        s_sqi[tid] = g_sq[i0 + tid];
        s_sqj[tid] = g_sq[j0 + tid];
    }

    // ldmatrix per-lane address precompute (byte offsets within 128x64h tile, 128B rows)
    const int laneA_row = lane & 15;
    const uint32_t baseA = (uint32_t)(((warp_m * 64 + laneA_row) << 7) + ((lane >> 4) << 4));
    const uint32_t xorA = (uint32_t)((laneA_row & 7) << 4);
    const int rowB = warp_n * 32 + ((lane >> 4) << 3) + (lane & 7);
    const uint32_t baseB = (uint32_t)((rowB << 7) + (((lane >> 3) & 1) << 4));
    const uint32_t xorB = (uint32_t)((rowB & 7) << 4);

    float c[4][4][4];
    #pragma unroll
    for (int mf = 0; mf < 4; mf++)
        #pragma unroll
        for (int nf = 0; nf < 4; nf++)
            #pragma unroll
            for (int r = 0; r < 4; r++) c[mf][nf][r] = 0.0f;

    unsigned simh[32];   // register-resident sim tile (fp16x2)

    const __half* AiL = g_lab_h + (size_t)i0 * CDIM;
    const __half* BjL = g_lab_h + (size_t)j0 * CDIM;
    const __half* AiO = g_out_h + (size_t)i0 * DDIM;
    const __half* BjO = g_out_h + (size_t)j0 * DDIM;

    // preload chunks 0 and 1 (separate commit groups)
    cpasync_tile(AiL, CDIM, 0, sb, tid);
    cpasync_tile(BjL, CDIM, 0, sb + 16384, tid);
    CP_COMMIT();
    cpasync_tile(AiL, CDIM, 64, sb + 32768, tid);
    cpasync_tile(BjL, CDIM, 64, sb + 32768 + 16384, tid);
    CP_COMMIT();

    // merged 6-chunk pipeline: chunks 0-1 = label gram, 2-5 = output gram
    // order per iteration: WAIT(ch) -> sync -> prefetch(ch+2) -> compute(ch)
    // the sync separates iteration ch-1's reads of buffer (ch-1)%3 from this
    // iteration's cp.async writes into the aliased (ch+2)%3  (R9 race fix)
    #pragma unroll 1
    for (int ch = 0; ch < 6; ch++) {
        if (ch < 5) CP_WAIT(1);     // chunk ch done, chunk ch+1 may stay in flight
        else        CP_WAIT(0);
        __syncthreads();

        if (ch + 2 < 6) {
            int nx = ch + 2;
            uint32_t nb = sb + (nx % 3) * 32768;
            if (nx < 2) {
                cpasync_tile(AiL, CDIM, nx * 64, nb, tid);
                cpasync_tile(BjL, CDIM, nx * 64, nb + 16384, tid);
            } else {
                cpasync_tile(AiO, DDIM, (nx - 2) * 64, nb, tid);
                cpasync_tile(BjO, DDIM, (nx - 2) * 64, nb + 16384, tid);
            }
            CP_COMMIT();
        }

        uint32_t sA = sb + (ch % 3) * 32768;
        uint32_t sB = sA + 16384;
        #pragma unroll
        for (int ks = 0; ks < 4; ks++) {
            uint4 a[4];
            #pragma unroll
            for (int mf = 0; mf < 4; mf++)
                a[mf] = ldsm_x4(sA + ((baseA + mf * 2048 + ks * 32) ^ xorA));
            uint4 b0 = ldsm_x4(sB + ((baseB + ks * 32) ^ xorB));
            uint4 b1 = ldsm_x4(sB + ((baseB + 2048 + ks * 32) ^ xorB));
            #pragma unroll
            for (int mf = 0; mf < 4; mf++) {
                mma16(c[mf][0], a[mf], b0.x, b0.y);
                mma16(c[mf][1], a[mf], b0.z, b0.w);
                mma16(c[mf][2], a[mf], b1.x, b1.y);
                mma16(c[mf][3], a[mf], b1.z, b1.w);
            }
        }
        if (ch == 1) {
            // epilogue A (overlaps in-flight copies): pack sim to regs, min/max, zero accums
            float lmin = 3.4e38f, lmax = -3.4e38f;
            #pragma unroll
            for (int mf = 0; mf < 4; mf++) {
                #pragma unroll
                for (int nf = 0; nf < 4; nf++) {
                    float v0 = c[mf][nf][0], v1 = c[mf][nf][1];
                    float v2 = c[mf][nf][2], v3 = c[mf][nf][3];
                    lmin = fminf(lmin, fminf(fminf(v0, v1), fminf(v2, v3)));
                    lmax = fmaxf(lmax, fmaxf(fmaxf(v0, v1), fmaxf(v2, v3)));
                    int idx0 = (mf * 4 + nf) * 2;
                    __half2 h01 = __floats2half2_rn(v0, v1);
                    __half2 h23 = __floats2half2_rn(v2, v3);
                    simh[idx0]     = *(unsigned*)&h01;
                    simh[idx0 + 1] = *(unsigned*)&h23;
                    c[mf][nf][0] = 0.0f; c[mf][nf][1] = 0.0f;
                    c[mf][nf][2] = 0.0f; c[mf][nf][3] = 0.0f;
                }
            }
            #pragma unroll
            for (int off = 16; off; off >>= 1) {
                lmin = fminf(lmin, __shfl_xor_sync(0xffffffffu, lmin, off));
                lmax = fmaxf(lmax, __shfl_xor_sync(0xffffffffu, lmax, off));
            }
            if (lane == 0) {
                atomicMin(&g_smin_enc, fenc(lmin));
                atomicMax(&g_smax_enc, fenc(lmax));
            }
        }
    }

    // epilogue B: eud + packed (sim|eud) store, upper tile only
    {
        float lemax = 0.0f;
        #pragma unroll
        for (int mf = 0; mf < 4; mf++) {
            int il = warp_m * 64 + mf * 16 + g;
            float q0 = s_sqi[il], q1 = s_sqi[il + 8];
            #pragma unroll
            for (int nf = 0; nf < 4; nf++) {
                int jl = warp_n * 32 + nf * 8 + 2 * tig;
                float r0 = s_sqj[jl], r1 = s_sqj[jl + 1];
                float d0 = q0 + r0 - 2.0f * c[mf][nf][0];
                float d1 = q0 + r1 - 2.0f * c[mf][nf][1];
                float d2_ = q1 + r0 - 2.0f * c[mf][nf][2];
                float d3 = q1 + r1 - 2.0f * c[mf][nf][3];
                float v0 = (d0 > 0.0f) ? sqrtaf(d0) : 0.0f;
                float v1 = (d1 > 0.0f) ? sqrtaf(d1) : 0.0f;
                float v2 = (d2_ > 0.0f) ? sqrtaf(d2_) : 0.0f;
                float v3 = (d3 > 0.0f) ? sqrtaf(d3) : 0.0f;
                if (i0 + il == j0 + jl) v0 = 0.0f;
                if (i0 + il == j0 + jl + 1) v1 = 0.0f;
                if (i0 + il + 8 == j0 + jl) v2 = 0.0f;
                if (i0 + il + 8 == j0 + jl + 1) v3 = 0.0f;
                lemax = fmaxf(lemax, fmaxf(fmaxf(v0, v1), fmaxf(v2, v3)));

                int idx0 = (mf * 4 + nf) * 2;
                unsigned sp01 = simh[idx0];
                unsigned sp23 = simh[idx0 + 1];
                unsigned u0 = pack_se(sp01, v0);
                unsigned u1 = pack_se(sp01 >> 16, v1);
                unsigned u2 = pack_se(sp23, v2);
                unsigned u3 = pack_se(sp23 >> 16, v3);

                *(uint2*)&g_se[(size_t)(i0 + il) * BSZ + j0 + jl]     = make_uint2(u0, u1);
                *(uint2*)&g_se[(size_t)(i0 + il + 8) * BSZ + j0 + jl] = make_uint2(u2, u3);
            }
        }
        #pragma unroll
        for (int off = 16; off; off >>= 1)
            lemax = fmaxf(lemax, __shfl_xor_sync(0xffffffffu, lemax, off));
        if (lane == 0) atomicMax(&g_emax_enc, fenc(lemax));
    }
}

// ---------------- kernel 3: tile loss (nc loads, capped regs) ----------------
__global__ __launch_bounds__(256, 6) void loss_tile_kernel() {
    int bi, bj;
    tri_decode((int)blockIdx.x, bi, bj);
    const int i0 = bi * TILE, j0 = bj * TILE;
    const int t = threadIdx.x;
    const int w = t >> 5, lane = t & 31;
    const int cg = lane & 15;        // 8-column group: cols cg*8 .. cg*8+7
    const int rhalf = lane >> 4;     // row within the pair

    const float L2E = 1.4426950408889634f;
    const float smin = fdec(g_smin_enc);
    const float smax = fdec(g_smax_enc);
    const float emax = fdec(g_emax_enc);
    const float c1 = L2E / (smax - smin);
    const float c0 = -smin * c1;
    const float c2 = L2E / emax;
    const float sthr = smin + 0.5f * (smax - smin);

    __shared__ float2 scol[8][128];

    float cp[8] = {0, 0, 0, 0, 0, 0, 0, 0};
    float cn[8] = {0, 0, 0, 0, 0, 0, 0, 0};

    #pragma unroll 1
    for (int it = 0; it < 8; it++) {
        const int row = w * 16 + it * 2 + rhalf;
        const char* base = (const char*)&g_se[(size_t)(i0 + row) * BSZ + j0 + cg * 8];
        uint4 v0 = ldg_nc4(base);
        uint4 v1 = ldg_nc4(base + 16);
        unsigned uu[8] = {v0.x, v0.y, v0.z, v0.w, v1.x, v1.y, v1.z, v1.w};
        float rp = 0.0f, rn = 0.0f;
        #pragma unroll
        for (int x = 0; x < 8; x++) {
            float2 f = __half22float2(*(__half2*)&uu[x]);   // f.x = sim, f.y = eud
            float d = fmaf(f.y, c2, fmaf(f.x, c1, c0));
            bool pos = f.x > sthr;
            float val = ex2f(pos ? d : (L2E - d));
            float vp = pos ? val : 0.0f;
            float vn = pos ? 0.0f : val;
            rp += vp; rn += vn;
            cp[x] += vp; cn[x] += vn;
        }
        #pragma unroll
        for (int off = 8; off; off >>= 1) {
            rp += __shfl_xor_sync(0xffffffffu, rp, off);
            rn += __shfl_xor_sync(0xffffffffu, rn, off);
        }
        if (cg == 0)
            g_part[(size_t)(i0 + row) * NTILE + bj] = make_float2(rp, rn);
    }

    // fold the two row-halves' column partials, then cross-warp reduce in smem
    #pragma unroll
    for (int x = 0; x < 8; x++) {
        cp[x] += __shfl_xor_sync(0xffffffffu, cp[x], 16);
        cn[x] += __shfl_xor_sync(0xffffffffu, cn[x], 16);
    }
    if (rhalf == 0) {
        #pragma unroll
        for (int x = 0; x < 8; x++) scol[w][cg * 8 + x] = make_float2(cp[x], cn[x]);
    }
    __syncthreads();
    if (bi != bj && t < 128) {
        float p = 0.0f, n = 0.0f;
        #pragma unroll
        for (int ww = 0; ww < 8; ww++) {
            float2 v = scol[ww][t];
            p += v.x; n += v.y;
        }
        g_part[(size_t)(j0 + t) * NTILE + bi] = make_float2(p, n);
    }
}

// ---------------- kernel 4: per-row reduce of partials -> rowloss ----------------
__global__ __launch_bounds__(128) void rowreduce_kernel() {
    const int row = blockIdx.x * 128 + threadIdx.x;
    const float2* p = &g_part[(size_t)row * NTILE];
    float P = 0.0f, N = 0.0f;
    #pragma unroll
    for (int k = 0; k < NTILE; k++) {
        float2 v = p[k];
        P += v.x; N += v.y;
    }
    float lp = fmaxf(logf(P), 0.0f);   // log(0) = -inf -> clamped to 0
    float ln = fmaxf(logf(N), 0.0f);
    g_rowloss[row] = lp + ln;
}

// ---------------- kernel 5: deterministic final mean ----------------
__global__ __launch_bounds__(256) void final_kernel(float* __restrict__ out) {
    __shared__ float s[256];
    const int t = threadIdx.x;
    float a = 0.0f;
    for (int i = t; i < BSZ; i += 256) a += g_rowloss[i];
    s[t] = a;
    __syncthreads();
    #pragma unroll
    for (int o = 128; o; o >>= 1) {
        if (t < o) s[t] += s[t + o];
        __syncthreads();
    }
    if (t == 0) out[0] = s[0] * (1.0f / (float)BSZ);
}

// ---------------- launch ----------------
extern "C" void kernel_launch(void* const* d_in, const int* in_sizes, int n_in,
                              void* d_out, int out_size) {
    const float* outputs = (const float*)d_in[0];
    const float* labels  = (const float*)d_in[1];
    if (n_in >= 2 && in_sizes[0] == BSZ * CDIM && in_sizes[1] == BSZ * DDIM) {
        const float* tmp = outputs; outputs = labels; labels = tmp;
    }
    float* out = (float*)d_out;

    cudaFuncSetAttribute(gram_mma, cudaFuncAttributeMaxDynamicSharedMemorySize, SM_BYTES);

    init_kernel<<<1, 1>>>();
    rowprep_kernel<<<BSZ / 8, 256>>>(outputs, labels);
    gram_mma<<<NPAIRS, 256, SM_BYTES>>>();
    loss_tile_kernel<<<NPAIRS, 256>>>();
    rowreduce_kernel<<<NTILE, 128>>>();
    final_kernel<<<1, 256>>>(out);
}

// round 11
// speedup vs baseline: 1.0427x; 1.0282x over previous
#include <cuda_runtime.h>
#include <cuda_fp16.h>
#include <cstdint>

#define BSZ 8192
#define CDIM 128
#define DDIM 256
#define TILE 128
#define NTILE 64          // BSZ / TILE
#define NPAIRS 2080       // NTILE*(NTILE+1)/2

// ---------------- scratch (static device globals; no allocation) ----------------
__device__ unsigned g_se[(size_t)BSZ * BSZ];    // packed (sim fp16 | eud fp16); upper tiles only
__device__ __half g_lab_h[(size_t)BSZ * CDIM];  // pre-normalized labels, fp16
__device__ __half g_out_h[(size_t)BSZ * DDIM];  // outputs, fp16
__device__ float g_sq[BSZ];                     // ||fp16(output_i)||^2 (fp32 accum)
__device__ float2 g_part[(size_t)BSZ * NTILE];  // per-(row, tile) partial (pos, neg) sums
__device__ float g_rowloss[BSZ];
__device__ unsigned g_smin_enc, g_smax_enc, g_emax_enc;

// monotone float <-> uint encoding so min/max reduce with integer atomics
__device__ __forceinline__ unsigned fenc(float f) {
    unsigned u = __float_as_uint(f);
    return (u & 0x80000000u) ? ~u : (u | 0x80000000u);
}
__device__ __forceinline__ float fdec(unsigned e) {
    unsigned u = (e & 0x80000000u) ? (e & 0x7FFFFFFFu) : ~e;
    return __uint_as_float(u);
}

// triangular pair decode: k in [0, NPAIRS) -> (a, b) with 0 <= a <= b < NTILE
__device__ __forceinline__ int tri_off(int a) { return a * NTILE - (a * (a - 1)) / 2; }
__device__ __forceinline__ void tri_decode(int k, int& a, int& b) {
    int aa = (int)((129.0f - sqrtf(16641.0f - 8.0f * (float)k)) * 0.5f);
    aa = max(0, min(63, aa));
    while (aa < 63 && tri_off(aa + 1) <= k) aa++;
    while (aa > 0 && tri_off(aa) > k) aa--;
    a = aa;
    b = aa + (k - tri_off(aa));
}

__device__ __forceinline__ uint32_t smem_u32(const void* p) {
    uint32_t a;
    asm("{ .reg .u64 t; cvta.to.shared.u64 t, %1; cvt.u32.u64 %0, t; }" : "=r"(a) : "l"(p));
    return a;
}
__device__ __forceinline__ uint4 ldsm_x4(uint32_t addr) {
    uint4 r;
    asm volatile("ldmatrix.sync.aligned.m8n8.x4.shared.b16 {%0,%1,%2,%3}, [%4];"
                 : "=r"(r.x), "=r"(r.y), "=r"(r.z), "=r"(r.w) : "r"(addr));
    return r;
}
__device__ __forceinline__ void mma16(float* c, uint4 a, uint32_t b0, uint32_t b1) {
    asm volatile(
        "mma.sync.aligned.m16n8k16.row.col.f32.f16.f16.f32 "
        "{%0,%1,%2,%3}, {%4,%5,%6,%7}, {%8,%9}, {%0,%1,%2,%3};"
        : "+f"(c[0]), "+f"(c[1]), "+f"(c[2]), "+f"(c[3])
        : "r"(a.x), "r"(a.y), "r"(a.z), "r"(a.w), "r"(b0), "r"(b1));
}
__device__ __forceinline__ float ex2f(float x) {
    float y;
    asm("ex2.approx.f32 %0, %1;" : "=f"(y) : "f"(x));
    return y;
}
__device__ __forceinline__ float sqrtaf(float x) {
    float y;
    asm("sqrt.approx.f32 %0, %1;" : "=f"(y) : "f"(x));
    return y;
}
__device__ __forceinline__ uint4 ldg_nc4(const void* p) {
    uint4 r;
    asm volatile("ld.global.nc.v4.u32 {%0,%1,%2,%3}, [%4];"
                 : "=r"(r.x), "=r"(r.y), "=r"(r.z), "=r"(r.w) : "l"(p));
    return r;
}
#define CP_ASYNC16(dst, src) \
    asm volatile("cp.async.cg.shared.global [%0], [%1], 16;" :: "r"(dst), "l"(src))
#define CP_COMMIT() asm volatile("cp.async.commit_group;" ::: "memory")
#define CP_WAIT(n)  asm volatile("cp.async.wait_group %0;" :: "n"(n) : "memory")

// ---------------- gram smem layout (bytes): 3 stages x 32KB + sq arrays ----------------
#define OFF_SQI   98304
#define OFF_SQJ   98816
#define SM_BYTES  99328

// copy one 128-row x 64-half tile into SW128-swizzled smem via cp.async
__device__ __forceinline__ void cpasync_tile(const __half* __restrict__ src, int ldh, int k0,
                                             uint32_t smem_dst, int tid) {
    #pragma unroll
    for (int it = 0; it < 4; it++) {
        int e = tid + 256 * it;                  // 0..1023 granules of 16B
        int row = e >> 3, gq = e & 7;
        const __half* g = src + (size_t)row * ldh + k0 + gq * 8;
        uint32_t bo = (uint32_t)(row * 128 + gq * 16);
        uint32_t dst = smem_dst + (bo ^ ((bo >> 3) & 0x70));
        CP_ASYNC16(dst, g);
    }
}

__device__ __forceinline__ unsigned pack_se(unsigned simlo16, float e) {
    unsigned eh = (unsigned)__half_as_ushort(__float2half_rn(e));
    return (simlo16 & 0xFFFFu) | (eh << 16);
}

// ---------------- kernel 1: per-row prep (absorbs init; warp-per-row, no block syncs) ----------------
__global__ __launch_bounds__(256) void rowprep_kernel(const float* __restrict__ outputs,
                                                      const float* __restrict__ labels) {
    if (blockIdx.x == 0 && threadIdx.x == 0) {
        g_smin_enc = fenc(3.4e38f);
        g_smax_enc = fenc(-3.4e38f);
        g_emax_enc = fenc(0.0f);
    }

    const int row = blockIdx.x * 8 + (threadIdx.x >> 5);
    const int lane = threadIdx.x & 31;

    // labels: 4 elements per lane
    float l[4];
    float lsum = 0.0f;
    #pragma unroll
    for (int x = 0; x < 4; x++) {
        l[x] = labels[(size_t)row * CDIM + lane + 32 * x];
        lsum += l[x] * l[x];
    }
    #pragma unroll
    for (int off = 16; off; off >>= 1) lsum += __shfl_xor_sync(0xffffffffu, lsum, off);
    float invn = 1.0f / (sqrtf(lsum) + 1e-12f);
    #pragma unroll
    for (int x = 0; x < 4; x++)
        g_lab_h[(size_t)row * CDIM + lane + 32 * x] = __float2half(l[x] * invn);

    // outputs: 8 elements per lane; sq from rounded values
    float osum = 0.0f;
    #pragma unroll
    for (int x = 0; x < 8; x++) {
        float o = outputs[(size_t)row * DDIM + lane + 32 * x];
        __half h = __float2half(o);
        g_out_h[(size_t)row * DDIM + lane + 32 * x] = h;
        float f = __half2float(h);
        osum += f * f;
    }
    #pragma unroll
    for (int off = 16; off; off >>= 1) osum += __shfl_xor_sync(0xffffffffu, osum, off);
    if (lane == 0) g_sq[row] = osum;
}

// ---------------- kernel 2: fp16 mma fused grams, race-free 3-stage pipeline ----------------
__global__ __launch_bounds__(256, 2) void gram_mma() {
    int bi, bj;
    tri_decode(blockIdx.x, bi, bj);
    extern __shared__ float sm[];
    const uint32_t sb = smem_u32(sm);
    float* s_sqi = (float*)((char*)sm + OFF_SQI);
    float* s_sqj = (float*)((char*)sm + OFF_SQJ);

    const int tid = threadIdx.x;
    const int wid = tid >> 5, lane = tid & 31;
    const int warp_m = wid >> 2, warp_n = wid & 3;
    const int g = lane >> 2, tig = lane & 3;
    const int i0 = bi * TILE, j0 = bj * TILE;

    if (tid < 128) {
        s_sqi[tid] = g_sq[i0 + tid];
        s_sqj[tid] = g_sq[j0 + tid];
    }

    // ldmatrix per-lane address precompute (byte offsets within 128x64h tile, 128B rows)
    const int laneA_row = lane & 15;
    const uint32_t baseA = (uint32_t)(((warp_m * 64 + laneA_row) << 7) + ((lane >> 4) << 4));
    const uint32_t xorA = (uint32_t)((laneA_row & 7) << 4);
    const int rowB = warp_n * 32 + ((lane >> 4) << 3) + (lane & 7);
    const uint32_t baseB = (uint32_t)((rowB << 7) + (((lane >> 3) & 1) << 4));
    const uint32_t xorB = (uint32_t)((rowB & 7) << 4);

    float c[4][4][4];
    #pragma unroll
    for (int mf = 0; mf < 4; mf++)
        #pragma unroll
        for (int nf = 0; nf < 4; nf++)
            #pragma unroll
            for (int r = 0; r < 4; r++) c[mf][nf][r] = 0.0f;

    unsigned simh[32];   // register-resident sim tile (fp16x2)

    const __half* AiL = g_lab_h + (size_t)i0 * CDIM;
    const __half* BjL = g_lab_h + (size_t)j0 * CDIM;
    const __half* AiO = g_out_h + (size_t)i0 * DDIM;
    const __half* BjO = g_out_h + (size_t)j0 * DDIM;

    // preload chunks 0 and 1 (separate commit groups)
    cpasync_tile(AiL, CDIM, 0, sb, tid);
    cpasync_tile(BjL, CDIM, 0, sb + 16384, tid);
    CP_COMMIT();
    cpasync_tile(AiL, CDIM, 64, sb + 32768, tid);
    cpasync_tile(BjL, CDIM, 64, sb + 32768 + 16384, tid);
    CP_COMMIT();

    // merged 6-chunk pipeline: chunks 0-1 = label gram, 2-5 = output gram
    // order per iteration: WAIT(ch) -> sync -> prefetch(ch+2) -> compute(ch)
    #pragma unroll 1
    for (int ch = 0; ch < 6; ch++) {
        if (ch < 5) CP_WAIT(1);
        else        CP_WAIT(0);
        __syncthreads();

        if (ch + 2 < 6) {
            int nx = ch + 2;
            uint32_t nb = sb + (nx % 3) * 32768;
            if (nx < 2) {
                cpasync_tile(AiL, CDIM, nx * 64, nb, tid);
                cpasync_tile(BjL, CDIM, nx * 64, nb + 16384, tid);
            } else {
                cpasync_tile(AiO, DDIM, (nx - 2) * 64, nb, tid);
                cpasync_tile(BjO, DDIM, (nx - 2) * 64, nb + 16384, tid);
            }
            CP_COMMIT();
        }

        uint32_t sA = sb + (ch % 3) * 32768;
        uint32_t sB = sA + 16384;
        #pragma unroll
        for (int ks = 0; ks < 4; ks++) {
            uint4 a[4];
            #pragma unroll
            for (int mf = 0; mf < 4; mf++)
                a[mf] = ldsm_x4(sA + ((baseA + mf * 2048 + ks * 32) ^ xorA));
            uint4 b0 = ldsm_x4(sB + ((baseB + ks * 32) ^ xorB));
            uint4 b1 = ldsm_x4(sB + ((baseB + 2048 + ks * 32) ^ xorB));
            #pragma unroll
            for (int mf = 0; mf < 4; mf++) {
                mma16(c[mf][0], a[mf], b0.x, b0.y);
                mma16(c[mf][1], a[mf], b0.z, b0.w);
                mma16(c[mf][2], a[mf], b1.x, b1.y);
                mma16(c[mf][3], a[mf], b1.z, b1.w);
            }
        }
        if (ch == 1) {
            // epilogue A (overlaps in-flight copies): pack sim to regs, min/max, zero accums
            float lmin = 3.4e38f, lmax = -3.4e38f;
            #pragma unroll
            for (int mf = 0; mf < 4; mf++) {
                #pragma unroll
                for (int nf = 0; nf < 4; nf++) {
                    float v0 = c[mf][nf][0], v1 = c[mf][nf][1];
                    float v2 = c[mf][nf][2], v3 = c[mf][nf][3];
                    lmin = fminf(lmin, fminf(fminf(v0, v1), fminf(v2, v3)));
                    lmax = fmaxf(lmax, fmaxf(fmaxf(v0, v1), fmaxf(v2, v3)));
                    int idx0 = (mf * 4 + nf) * 2;
                    __half2 h01 = __floats2half2_rn(v0, v1);
                    __half2 h23 = __floats2half2_rn(v2, v3);
                    simh[idx0]     = *(unsigned*)&h01;
                    simh[idx0 + 1] = *(unsigned*)&h23;
                    c[mf][nf][0] = 0.0f; c[mf][nf][1] = 0.0f;
                    c[mf][nf][2] = 0.0f; c[mf][nf][3] = 0.0f;
                }
            }
            #pragma unroll
            for (int off = 16; off; off >>= 1) {
                lmin = fminf(lmin, __shfl_xor_sync(0xffffffffu, lmin, off));
                lmax = fmaxf(lmax, __shfl_xor_sync(0xffffffffu, lmax, off));
            }
            if (lane == 0) {
                atomicMin(&g_smin_enc, fenc(lmin));
                atomicMax(&g_smax_enc, fenc(lmax));
            }
        }
    }

    // epilogue B: eud + packed (sim|eud) store, upper tile only
    {
        float lemax = 0.0f;
        #pragma unroll
        for (int mf = 0; mf < 4; mf++) {
            int il = warp_m * 64 + mf * 16 + g;
            float q0 = s_sqi[il], q1 = s_sqi[il + 8];
            #pragma unroll
            for (int nf = 0; nf < 4; nf++) {
                int jl = warp_n * 32 + nf * 8 + 2 * tig;
                float r0 = s_sqj[jl], r1 = s_sqj[jl + 1];
                float d0 = q0 + r0 - 2.0f * c[mf][nf][0];
                float d1 = q0 + r1 - 2.0f * c[mf][nf][1];
                float d2_ = q1 + r0 - 2.0f * c[mf][nf][2];
                float d3 = q1 + r1 - 2.0f * c[mf][nf][3];
                float v0 = (d0 > 0.0f) ? sqrtaf(d0) : 0.0f;
                float v1 = (d1 > 0.0f) ? sqrtaf(d1) : 0.0f;
                float v2 = (d2_ > 0.0f) ? sqrtaf(d2_) : 0.0f;
                float v3 = (d3 > 0.0f) ? sqrtaf(d3) : 0.0f;
                if (i0 + il == j0 + jl) v0 = 0.0f;
                if (i0 + il == j0 + jl + 1) v1 = 0.0f;
                if (i0 + il + 8 == j0 + jl) v2 = 0.0f;
                if (i0 + il + 8 == j0 + jl + 1) v3 = 0.0f;
                lemax = fmaxf(lemax, fmaxf(fmaxf(v0, v1), fmaxf(v2, v3)));

                int idx0 = (mf * 4 + nf) * 2;
                unsigned sp01 = simh[idx0];
                unsigned sp23 = simh[idx0 + 1];
                unsigned u0 = pack_se(sp01, v0);
                unsigned u1 = pack_se(sp01 >> 16, v1);
                unsigned u2 = pack_se(sp23, v2);
                unsigned u3 = pack_se(sp23 >> 16, v3);

                *(uint2*)&g_se[(size_t)(i0 + il) * BSZ + j0 + jl]     = make_uint2(u0, u1);
                *(uint2*)&g_se[(size_t)(i0 + il + 8) * BSZ + j0 + jl] = make_uint2(u2, u3);
            }
        }
        #pragma unroll
        for (int off = 16; off; off >>= 1)
            lemax = fmaxf(lemax, __shfl_xor_sync(0xffffffffu, lemax, off));
        if (lane == 0) atomicMax(&g_emax_enc, fenc(lemax));
    }
}

// ---------------- kernel 3: tile loss — batched shfl reductions, prefetched loads ----------------
__global__ __launch_bounds__(256, 4) void loss_tile_kernel() {
    int bi, bj;
    tri_decode((int)blockIdx.x, bi, bj);
    const int i0 = bi * TILE, j0 = bj * TILE;
    const int t = threadIdx.x;
    const int w = t >> 5, lane = t & 31;
    const int cg = lane & 15;        // 8-column group: cols cg*8 .. cg*8+7
    const int rhalf = lane >> 4;     // row within the pair

    const float L2E = 1.4426950408889634f;
    const float smin = fdec(g_smin_enc);
    const float smax = fdec(g_smax_enc);
    const float emax = fdec(g_emax_enc);
    const float c1 = L2E / (smax - smin);
    const float c0 = -smin * c1;
    const float c2 = L2E / emax;
    const float sthr = smin + 0.5f * (smax - smin);

    __shared__ float2 scol[8][128];

    float cp[8] = {0, 0, 0, 0, 0, 0, 0, 0};
    float cn[8] = {0, 0, 0, 0, 0, 0, 0, 0};
    float rp[8], rn[8];

    const char* base0 = (const char*)&g_se[(size_t)(i0 + w * 16 + rhalf) * BSZ + j0 + cg * 8];
    const size_t rstep = (size_t)2 * BSZ * 4;   // 2 rows per iteration, 4B per element

    uint4 v0 = ldg_nc4(base0);
    uint4 v1 = ldg_nc4(base0 + 16);

    #pragma unroll
    for (int it = 0; it < 8; it++) {
        uint4 a0 = v0, a1 = v1;
        if (it < 7) {
            const char* nb = base0 + (size_t)(it + 1) * rstep;
            v0 = ldg_nc4(nb);
            v1 = ldg_nc4(nb + 16);
        }
        unsigned uu[8] = {a0.x, a0.y, a0.z, a0.w, a1.x, a1.y, a1.z, a1.w};
        float p = 0.0f, n = 0.0f;
        #pragma unroll
        for (int x = 0; x < 8; x++) {
            float2 f = __half22float2(*(__half2*)&uu[x]);   // f.x = sim, f.y = eud
            float d = fmaf(f.y, c2, fmaf(f.x, c1, c0));
            bool pos = f.x > sthr;
            float val = ex2f(pos ? d : (L2E - d));
            float vp = pos ? val : 0.0f;
            float vn = pos ? 0.0f : val;
            p += vp; n += vn;
            cp[x] += vp; cn[x] += vn;
        }
        rp[it] = p;
        rn[it] = n;
    }

    // batched row reductions: 16 independent shfl chains pipeline through the unit
    #pragma unroll
    for (int off = 8; off; off >>= 1) {
        #pragma unroll
        for (int it = 0; it < 8; it++) {
            rp[it] += __shfl_xor_sync(0xffffffffu, rp[it], off);
            rn[it] += __shfl_xor_sync(0xffffffffu, rn[it], off);
        }
    }
    if (cg == 0) {
        #pragma unroll
        for (int it = 0; it < 8; it++) {
            int row = w * 16 + it * 2 + rhalf;
            g_part[(size_t)(i0 + row) * NTILE + bj] = make_float2(rp[it], rn[it]);
        }
    }

    // fold the two row-halves' column partials, then cross-warp reduce in smem
    #pragma unroll
    for (int x = 0; x < 8; x++) {
        cp[x] += __shfl_xor_sync(0xffffffffu, cp[x], 16);
        cn[x] += __shfl_xor_sync(0xffffffffu, cn[x], 16);
    }
    if (rhalf == 0) {
        #pragma unroll
        for (int x = 0; x < 8; x++) scol[w][cg * 8 + x] = make_float2(cp[x], cn[x]);
    }
    __syncthreads();
    if (bi != bj && t < 128) {
        float p = 0.0f, n = 0.0f;
        #pragma unroll
        for (int ww = 0; ww < 8; ww++) {
            float2 v = scol[ww][t];
            p += v.x; n += v.y;
        }
        g_part[(size_t)(j0 + t) * NTILE + bi] = make_float2(p, n);
    }
}

// ---------------- kernel 4: per-row reduce of partials -> rowloss ----------------
__global__ __launch_bounds__(128) void rowreduce_kernel() {
    const int row = blockIdx.x * 128 + threadIdx.x;
    const float2* p = &g_part[(size_t)row * NTILE];
    float P = 0.0f, N = 0.0f;
    #pragma unroll
    for (int k = 0; k < NTILE; k++) {
        float2 v = p[k];
        P += v.x; N += v.y;
    }
    float lp = fmaxf(logf(P), 0.0f);   // log(0) = -inf -> clamped to 0
    float ln = fmaxf(logf(N), 0.0f);
    g_rowloss[row] = lp + ln;
}

// ---------------- kernel 5: deterministic final mean ----------------
__global__ __launch_bounds__(256) void final_kernel(float* __restrict__ out) {
    __shared__ float s[256];
    const int t = threadIdx.x;
    float a = 0.0f;
    for (int i = t; i < BSZ; i += 256) a += g_rowloss[i];
    s[t] = a;
    __syncthreads();
    #pragma unroll
    for (int o = 128; o; o >>= 1) {
        if (t < o) s[t] += s[t + o];
        __syncthreads();
    }
    if (t == 0) out[0] = s[0] * (1.0f / (float)BSZ);
}

// ---------------- launch ----------------
extern "C" void kernel_launch(void* const* d_in, const int* in_sizes, int n_in,
                              void* d_out, int out_size) {
    const float* outputs = (const float*)d_in[0];
    const float* labels  = (const float*)d_in[1];
    if (n_in >= 2 && in_sizes[0] == BSZ * CDIM && in_sizes[1] == BSZ * DDIM) {
        const float* tmp = outputs; outputs = labels; labels = tmp;
    }
    float* out = (float*)d_out;

    cudaFuncSetAttribute(gram_mma, cudaFuncAttributeMaxDynamicSharedMemorySize, SM_BYTES);

    rowprep_kernel<<<BSZ / 8, 256>>>(outputs, labels);
    gram_mma<<<NPAIRS, 256, SM_BYTES>>>();
    loss_tile_kernel<<<NPAIRS, 256>>>();
    rowreduce_kernel<<<NTILE, 128>>>();
    final_kernel<<<1, 256>>>(out);
}

// round 12
// speedup vs baseline: 1.0561x; 1.0129x over previous
#include <cuda_runtime.h>
#include <cuda_fp16.h>
#include <cstdint>

#define BSZ 8192
#define CDIM 128
#define DDIM 256
#define TILE 128
#define NTILE 64          // BSZ / TILE
#define NPAIRS 2080       // NTILE*(NTILE+1)/2

// ---------------- scratch (static device globals; no allocation) ----------------
__device__ unsigned g_se[(size_t)BSZ * BSZ];    // packed (sim fp16 | eud fp16); upper tiles only
__device__ __half g_lab_h[(size_t)BSZ * CDIM];  // pre-normalized labels, fp16
__device__ __half g_out_h[(size_t)BSZ * DDIM];  // outputs, fp16
__device__ float g_sq[BSZ];                     // ||fp16(output_i)||^2 (fp32 accum)
__device__ float2 g_part[(size_t)NTILE * BSZ];  // per-(tile, row) partial sums (TILE-MAJOR)
__device__ float g_rowloss[BSZ];
__device__ unsigned g_smin_enc, g_smax_enc, g_emax_enc;

// monotone float <-> uint encoding so min/max reduce with integer atomics
__device__ __forceinline__ unsigned fenc(float f) {
    unsigned u = __float_as_uint(f);
    return (u & 0x80000000u) ? ~u : (u | 0x80000000u);
}
__device__ __forceinline__ float fdec(unsigned e) {
    unsigned u = (e & 0x80000000u) ? (e & 0x7FFFFFFFu) : ~e;
    return __uint_as_float(u);
}

// triangular pair decode: k in [0, NPAIRS) -> (a, b) with 0 <= a <= b < NTILE
__device__ __forceinline__ int tri_off(int a) { return a * NTILE - (a * (a - 1)) / 2; }
__device__ __forceinline__ void tri_decode(int k, int& a, int& b) {
    int aa = (int)((129.0f - sqrtf(16641.0f - 8.0f * (float)k)) * 0.5f);
    aa = max(0, min(63, aa));
    while (aa < 63 && tri_off(aa + 1) <= k) aa++;
    while (aa > 0 && tri_off(aa) > k) aa--;
    a = aa;
    b = aa + (k - tri_off(aa));
}

__device__ __forceinline__ uint32_t smem_u32(const void* p) {
    uint32_t a;
    asm("{ .reg .u64 t; cvta.to.shared.u64 t, %1; cvt.u32.u64 %0, t; }" : "=r"(a) : "l"(p));
    return a;
}
__device__ __forceinline__ uint4 ldsm_x4(uint32_t addr) {
    uint4 r;
    asm volatile("ldmatrix.sync.aligned.m8n8.x4.shared.b16 {%0,%1,%2,%3}, [%4];"
                 : "=r"(r.x), "=r"(r.y), "=r"(r.z), "=r"(r.w) : "r"(addr));
    return r;
}
__device__ __forceinline__ void mma16(float* c, uint4 a, uint32_t b0, uint32_t b1) {
    asm volatile(
        "mma.sync.aligned.m16n8k16.row.col.f32.f16.f16.f32 "
        "{%0,%1,%2,%3}, {%4,%5,%6,%7}, {%8,%9}, {%0,%1,%2,%3};"
        : "+f"(c[0]), "+f"(c[1]), "+f"(c[2]), "+f"(c[3])
        : "r"(a.x), "r"(a.y), "r"(a.z), "r"(a.w), "r"(b0), "r"(b1));
}
__device__ __forceinline__ float ex2f(float x) {
    float y;
    asm("ex2.approx.f32 %0, %1;" : "=f"(y) : "f"(x));
    return y;
}
__device__ __forceinline__ float sqrtaf(float x) {
    float y;
    asm("sqrt.approx.f32 %0, %1;" : "=f"(y) : "f"(x));
    return y;
}
__device__ __forceinline__ uint4 ldg_nc4(const void* p) {
    uint4 r;
    asm volatile("ld.global.nc.v4.u32 {%0,%1,%2,%3}, [%4];"
                 : "=r"(r.x), "=r"(r.y), "=r"(r.z), "=r"(r.w) : "l"(p));
    return r;
}
#define CP_ASYNC16(dst, src) \
    asm volatile("cp.async.cg.shared.global [%0], [%1], 16;" :: "r"(dst), "l"(src))
#define CP_COMMIT() asm volatile("cp.async.commit_group;" ::: "memory")
#define CP_WAIT(n)  asm volatile("cp.async.wait_group %0;" :: "n"(n) : "memory")

// ---------------- gram smem layout (bytes): 3 stages x 32KB + sq arrays ----------------
#define OFF_SQI   98304
#define OFF_SQJ   98816
#define SM_BYTES  99328

// copy one 128-row x 64-half tile into SW128-swizzled smem via cp.async
__device__ __forceinline__ void cpasync_tile(const __half* __restrict__ src, int ldh, int k0,
                                             uint32_t smem_dst, int tid) {
    #pragma unroll
    for (int it = 0; it < 4; it++) {
        int e = tid + 256 * it;                  // 0..1023 granules of 16B
        int row = e >> 3, gq = e & 7;
        const __half* g = src + (size_t)row * ldh + k0 + gq * 8;
        uint32_t bo = (uint32_t)(row * 128 + gq * 16);
        uint32_t dst = smem_dst + (bo ^ ((bo >> 3) & 0x70));
        CP_ASYNC16(dst, g);
    }
}

__device__ __forceinline__ unsigned pack_se(unsigned simlo16, float e) {
    unsigned eh = (unsigned)__half_as_ushort(__float2half_rn(e));
    return (simlo16 & 0xFFFFu) | (eh << 16);
}

// ---------------- kernel 1: per-row prep (absorbs init; warp-per-row, no block syncs) ----------------
__global__ __launch_bounds__(256) void rowprep_kernel(const float* __restrict__ outputs,
                                                      const float* __restrict__ labels) {
    if (blockIdx.x == 0 && threadIdx.x == 0) {
        g_smin_enc = fenc(3.4e38f);
        g_smax_enc = fenc(-3.4e38f);
        g_emax_enc = fenc(0.0f);
    }

    const int row = blockIdx.x * 8 + (threadIdx.x >> 5);
    const int lane = threadIdx.x & 31;

    // labels: 4 elements per lane
    float l[4];
    float lsum = 0.0f;
    #pragma unroll
    for (int x = 0; x < 4; x++) {
        l[x] = labels[(size_t)row * CDIM + lane + 32 * x];
        lsum += l[x] * l[x];
    }
    #pragma unroll
    for (int off = 16; off; off >>= 1) lsum += __shfl_xor_sync(0xffffffffu, lsum, off);
    float invn = 1.0f / (sqrtf(lsum) + 1e-12f);
    #pragma unroll
    for (int x = 0; x < 4; x++)
        g_lab_h[(size_t)row * CDIM + lane + 32 * x] = __float2half(l[x] * invn);

    // outputs: 8 elements per lane; sq from rounded values
    float osum = 0.0f;
    #pragma unroll
    for (int x = 0; x < 8; x++) {
        float o = outputs[(size_t)row * DDIM + lane + 32 * x];
        __half h = __float2half(o);
        g_out_h[(size_t)row * DDIM + lane + 32 * x] = h;
        float f = __half2float(h);
        osum += f * f;
    }
    #pragma unroll
    for (int off = 16; off; off >>= 1) osum += __shfl_xor_sync(0xffffffffu, osum, off);
    if (lane == 0) g_sq[row] = osum;
}

// ---------------- kernel 2: fp16 mma fused grams, race-free 3-stage pipeline ----------------
__global__ __launch_bounds__(256, 2) void gram_mma() {
    int bi, bj;
    tri_decode(blockIdx.x, bi, bj);
    extern __shared__ float sm[];
    const uint32_t sb = smem_u32(sm);
    float* s_sqi = (float*)((char*)sm + OFF_SQI);
    float* s_sqj = (float*)((char*)sm + OFF_SQJ);

    const int tid = threadIdx.x;
    const int wid = tid >> 5, lane = tid & 31;
    const int warp_m = wid >> 2, warp_n = wid & 3;
    const int g = lane >> 2, tig = lane & 3;
    const int i0 = bi * TILE, j0 = bj * TILE;

    if (tid < 128) {
        s_sqi[tid] = g_sq[i0 + tid];
        s_sqj[tid] = g_sq[j0 + tid];
    }

    // ldmatrix per-lane address precompute (byte offsets within 128x64h tile, 128B rows)
    const int laneA_row = lane & 15;
    const uint32_t baseA = (uint32_t)(((warp_m * 64 + laneA_row) << 7) + ((lane >> 4) << 4));
    const uint32_t xorA = (uint32_t)((laneA_row & 7) << 4);
    const int rowB = warp_n * 32 + ((lane >> 4) << 3) + (lane & 7);
    const uint32_t baseB = (uint32_t)((rowB << 7) + (((lane >> 3) & 1) << 4));
    const uint32_t xorB = (uint32_t)((rowB & 7) << 4);

    float c[4][4][4];
    #pragma unroll
    for (int mf = 0; mf < 4; mf++)
        #pragma unroll
        for (int nf = 0; nf < 4; nf++)
            #pragma unroll
            for (int r = 0; r < 4; r++) c[mf][nf][r] = 0.0f;

    unsigned simh[32];   // register-resident sim tile (fp16x2)

    const __half* AiL = g_lab_h + (size_t)i0 * CDIM;
    const __half* BjL = g_lab_h + (size_t)j0 * CDIM;
    const __half* AiO = g_out_h + (size_t)i0 * DDIM;
    const __half* BjO = g_out_h + (size_t)j0 * DDIM;

    // preload chunks 0 and 1 (separate commit groups)
    cpasync_tile(AiL, CDIM, 0, sb, tid);
    cpasync_tile(BjL, CDIM, 0, sb + 16384, tid);
    CP_COMMIT();
    cpasync_tile(AiL, CDIM, 64, sb + 32768, tid);
    cpasync_tile(BjL, CDIM, 64, sb + 32768 + 16384, tid);
    CP_COMMIT();

    // merged 6-chunk pipeline: chunks 0-1 = label gram, 2-5 = output gram
    // order per iteration: WAIT(ch) -> sync -> prefetch(ch+2) -> compute(ch)
    #pragma unroll 1
    for (int ch = 0; ch < 6; ch++) {
        if (ch < 5) CP_WAIT(1);
        else        CP_WAIT(0);
        __syncthreads();

        if (ch + 2 < 6) {
            int nx = ch + 2;
            uint32_t nb = sb + (nx % 3) * 32768;
            if (nx < 2) {
                cpasync_tile(AiL, CDIM, nx * 64, nb, tid);
                cpasync_tile(BjL, CDIM, nx * 64, nb + 16384, tid);
            } else {
                cpasync_tile(AiO, DDIM, (nx - 2) * 64, nb, tid);
                cpasync_tile(BjO, DDIM, (nx - 2) * 64, nb + 16384, tid);
            }
            CP_COMMIT();
        }

        uint32_t sA = sb + (ch % 3) * 32768;
        uint32_t sB = sA + 16384;
        #pragma unroll
        for (int ks = 0; ks < 4; ks++) {
            uint4 a[4];
            #pragma unroll
            for (int mf = 0; mf < 4; mf++)
                a[mf] = ldsm_x4(sA + ((baseA + mf * 2048 + ks * 32) ^ xorA));
            uint4 b0 = ldsm_x4(sB + ((baseB + ks * 32) ^ xorB));
            uint4 b1 = ldsm_x4(sB + ((baseB + 2048 + ks * 32) ^ xorB));
            #pragma unroll
            for (int mf = 0; mf < 4; mf++) {
                mma16(c[mf][0], a[mf], b0.x, b0.y);
                mma16(c[mf][1], a[mf], b0.z, b0.w);
                mma16(c[mf][2], a[mf], b1.x, b1.y);
                mma16(c[mf][3], a[mf], b1.z, b1.w);
            }
        }
        if (ch == 1) {
            // epilogue A (overlaps in-flight copies): pack sim to regs, min/max, zero accums
            float lmin = 3.4e38f, lmax = -3.4e38f;
            #pragma unroll
            for (int mf = 0; mf < 4; mf++) {
                #pragma unroll
                for (int nf = 0; nf < 4; nf++) {
                    float v0 = c[mf][nf][0], v1 = c[mf][nf][1];
                    float v2 = c[mf][nf][2], v3 = c[mf][nf][3];
                    lmin = fminf(lmin, fminf(fminf(v0, v1), fminf(v2, v3)));
                    lmax = fmaxf(lmax, fmaxf(fmaxf(v0, v1), fmaxf(v2, v3)));
                    int idx0 = (mf * 4 + nf) * 2;
                    __half2 h01 = __floats2half2_rn(v0, v1);
                    __half2 h23 = __floats2half2_rn(v2, v3);
                    simh[idx0]     = *(unsigned*)&h01;
                    simh[idx0 + 1] = *(unsigned*)&h23;
                    c[mf][nf][0] = 0.0f; c[mf][nf][1] = 0.0f;
                    c[mf][nf][2] = 0.0f; c[mf][nf][3] = 0.0f;
                }
            }
            #pragma unroll
            for (int off = 16; off; off >>= 1) {
                lmin = fminf(lmin, __shfl_xor_sync(0xffffffffu, lmin, off));
                lmax = fmaxf(lmax, __shfl_xor_sync(0xffffffffu, lmax, off));
            }
            if (lane == 0) {
                atomicMin(&g_smin_enc, fenc(lmin));
                atomicMax(&g_smax_enc, fenc(lmax));
            }
        }
    }

    // epilogue B: eud + packed (sim|eud) store, upper tile only
    {
        float lemax = 0.0f;
        #pragma unroll
        for (int mf = 0; mf < 4; mf++) {
            int il = warp_m * 64 + mf * 16 + g;
            float q0 = s_sqi[il], q1 = s_sqi[il + 8];
            #pragma unroll
            for (int nf = 0; nf < 4; nf++) {
                int jl = warp_n * 32 + nf * 8 + 2 * tig;
                float r0 = s_sqj[jl], r1 = s_sqj[jl + 1];
                float d0 = q0 + r0 - 2.0f * c[mf][nf][0];
                float d1 = q0 + r1 - 2.0f * c[mf][nf][1];
                float d2_ = q1 + r0 - 2.0f * c[mf][nf][2];
                float d3 = q1 + r1 - 2.0f * c[mf][nf][3];
                float v0 = (d0 > 0.0f) ? sqrtaf(d0) : 0.0f;
                float v1 = (d1 > 0.0f) ? sqrtaf(d1) : 0.0f;
                float v2 = (d2_ > 0.0f) ? sqrtaf(d2_) : 0.0f;
                float v3 = (d3 > 0.0f) ? sqrtaf(d3) : 0.0f;
                if (i0 + il == j0 + jl) v0 = 0.0f;
                if (i0 + il == j0 + jl + 1) v1 = 0.0f;
                if (i0 + il + 8 == j0 + jl) v2 = 0.0f;
                if (i0 + il + 8 == j0 + jl + 1) v3 = 0.0f;
                lemax = fmaxf(lemax, fmaxf(fmaxf(v0, v1), fmaxf(v2, v3)));

                int idx0 = (mf * 4 + nf) * 2;
                unsigned sp01 = simh[idx0];
                unsigned sp23 = simh[idx0 + 1];
                unsigned u0 = pack_se(sp01, v0);
                unsigned u1 = pack_se(sp01 >> 16, v1);
                unsigned u2 = pack_se(sp23, v2);
                unsigned u3 = pack_se(sp23 >> 16, v3);

                *(uint2*)&g_se[(size_t)(i0 + il) * BSZ + j0 + jl]     = make_uint2(u0, u1);
                *(uint2*)&g_se[(size_t)(i0 + il + 8) * BSZ + j0 + jl] = make_uint2(u2, u3);
            }
        }
        #pragma unroll
        for (int off = 16; off; off >>= 1)
            lemax = fmaxf(lemax, __shfl_xor_sync(0xffffffffu, lemax, off));
        if (lane == 0) atomicMax(&g_emax_enc, fenc(lemax));
    }
}

// ---------------- kernel 3: tile loss — batched shfl reductions, prefetched loads ----------------
__global__ __launch_bounds__(256, 4) void loss_tile_kernel() {
    int bi, bj;
    tri_decode((int)blockIdx.x, bi, bj);
    const int i0 = bi * TILE, j0 = bj * TILE;
    const int t = threadIdx.x;
    const int w = t >> 5, lane = t & 31;
    const int cg = lane & 15;        // 8-column group: cols cg*8 .. cg*8+7
    const int rhalf = lane >> 4;     // row within the pair

    const float L2E = 1.4426950408889634f;
    const float smin = fdec(g_smin_enc);
    const float smax = fdec(g_smax_enc);
    const float emax = fdec(g_emax_enc);
    const float c1 = L2E / (smax - smin);
    const float c0 = -smin * c1;
    const float c2 = L2E / emax;
    const float sthr = smin + 0.5f * (smax - smin);

    __shared__ float2 scol[8][128];

    float cp[8] = {0, 0, 0, 0, 0, 0, 0, 0};
    float cn[8] = {0, 0, 0, 0, 0, 0, 0, 0};
    float rp[8], rn[8];

    const char* base0 = (const char*)&g_se[(size_t)(i0 + w * 16 + rhalf) * BSZ + j0 + cg * 8];
    const size_t rstep = (size_t)2 * BSZ * 4;   // 2 rows per iteration, 4B per element

    uint4 v0 = ldg_nc4(base0);
    uint4 v1 = ldg_nc4(base0 + 16);

    #pragma unroll
    for (int it = 0; it < 8; it++) {
        uint4 a0 = v0, a1 = v1;
        if (it < 7) {
            const char* nb = base0 + (size_t)(it + 1) * rstep;
            v0 = ldg_nc4(nb);
            v1 = ldg_nc4(nb + 16);
        }
        unsigned uu[8] = {a0.x, a0.y, a0.z, a0.w, a1.x, a1.y, a1.z, a1.w};
        float p = 0.0f, n = 0.0f;
        #pragma unroll
        for (int x = 0; x < 8; x++) {
            float2 f = __half22float2(*(__half2*)&uu[x]);   // f.x = sim, f.y = eud
            float d = fmaf(f.y, c2, fmaf(f.x, c1, c0));
            bool pos = f.x > sthr;
            float val = ex2f(pos ? d : (L2E - d));
            float vp = pos ? val : 0.0f;
            float vn = pos ? 0.0f : val;
            p += vp; n += vn;
            cp[x] += vp; cn[x] += vn;
        }
        rp[it] = p;
        rn[it] = n;
    }

    // batched row reductions: 16 independent shfl chains pipeline through the unit
    #pragma unroll
    for (int off = 8; off; off >>= 1) {
        #pragma unroll
        for (int it = 0; it < 8; it++) {
            rp[it] += __shfl_xor_sync(0xffffffffu, rp[it], off);
            rn[it] += __shfl_xor_sync(0xffffffffu, rn[it], off);
        }
    }
    if (cg == 0) {
        #pragma unroll
        for (int it = 0; it < 8; it++) {
            int row = w * 16 + it * 2 + rhalf;
            g_part[(size_t)bj * BSZ + i0 + row] = make_float2(rp[it], rn[it]);
        }
    }

    // fold the two row-halves' column partials, then cross-warp reduce in smem
    #pragma unroll
    for (int x = 0; x < 8; x++) {
        cp[x] += __shfl_xor_sync(0xffffffffu, cp[x], 16);
        cn[x] += __shfl_xor_sync(0xffffffffu, cn[x], 16);
    }
    if (rhalf == 0) {
        #pragma unroll
        for (int x = 0; x < 8; x++) scol[w][cg * 8 + x] = make_float2(cp[x], cn[x]);
    }
    __syncthreads();
    if (bi != bj && t < 128) {
        float p = 0.0f, n = 0.0f;
        #pragma unroll
        for (int ww = 0; ww < 8; ww++) {
            float2 v = scol[ww][t];
            p += v.x; n += v.y;
        }
        g_part[(size_t)bi * BSZ + j0 + t] = make_float2(p, n);
    }
}

// ---------------- kernel 4: per-row reduce of partials (tile-major, coalesced, MLP-16) ----------------
__global__ __launch_bounds__(128) void rowreduce_kernel() {
    const int row = blockIdx.x * 128 + threadIdx.x;
    float P = 0.0f, N = 0.0f;
    #pragma unroll
    for (int k0 = 0; k0 < NTILE; k0 += 16) {
        float2 v[16];
        #pragma unroll
        for (int k = 0; k < 16; k++)
            v[k] = g_part[(size_t)(k0 + k) * BSZ + row];
        #pragma unroll
        for (int k = 0; k < 16; k++) { P += v[k].x; N += v[k].y; }
    }
    float lp = fmaxf(logf(P), 0.0f);   // log(0) = -inf -> clamped to 0
    float ln = fmaxf(logf(N), 0.0f);
    g_rowloss[row] = lp + ln;
}

// ---------------- kernel 5: deterministic final mean ----------------
__global__ __launch_bounds__(256) void final_kernel(float* __restrict__ out) {
    __shared__ float s[256];
    const int t = threadIdx.x;
    float a = 0.0f;
    for (int i = t; i < BSZ; i += 256) a += g_rowloss[i];
    s[t] = a;
    __syncthreads();
    #pragma unroll
    for (int o = 128; o; o >>= 1) {
        if (t < o) s[t] += s[t + o];
        __syncthreads();
    }
    if (t == 0) out[0] = s[0] * (1.0f / (float)BSZ);
}

// ---------------- launch ----------------
extern "C" void kernel_launch(void* const* d_in, const int* in_sizes, int n_in,
                              void* d_out, int out_size) {
    const float* outputs = (const float*)d_in[0];
    const float* labels  = (const float*)d_in[1];
    if (n_in >= 2 && in_sizes[0] == BSZ * CDIM && in_sizes[1] == BSZ * DDIM) {
        const float* tmp = outputs; outputs = labels; labels = tmp;
    }
    float* out = (float*)d_out;

    cudaFuncSetAttribute(gram_mma, cudaFuncAttributeMaxDynamicSharedMemorySize, SM_BYTES);

    rowprep_kernel<<<BSZ / 8, 256>>>(outputs, labels);
    gram_mma<<<NPAIRS, 256, SM_BYTES>>>();
    loss_tile_kernel<<<NPAIRS, 256>>>();
    rowreduce_kernel<<<NTILE, 128>>>();
    final_kernel<<<1, 256>>>(out);
}

// round 13
// speedup vs baseline: 1.0729x; 1.0158x over previous
#include <cuda_runtime.h>
#include <cuda_fp16.h>
#include <cstdint>

#define BSZ 8192
#define CDIM 128
#define DDIM 256
#define TILE 128
#define NTILE 64          // BSZ / TILE
#define NPAIRS 2080       // NTILE*(NTILE+1)/2

// ---------------- scratch (static device globals; no allocation) ----------------
__device__ unsigned g_se[(size_t)BSZ * BSZ];    // packed (sim fp16 | eud fp16); upper tiles only
__device__ __half g_lab_h[(size_t)BSZ * CDIM];  // pre-normalized labels, fp16
__device__ __half g_out_h[(size_t)BSZ * DDIM];  // outputs, fp16
__device__ float g_sq[BSZ];                     // ||fp16(output_i)||^2 (fp32 accum)
__device__ float2 g_part[(size_t)NTILE * BSZ];  // per-(tile, row) partial sums (TILE-MAJOR)
__device__ float g_rowloss[BSZ];
__device__ unsigned g_smin_enc, g_smax_enc, g_emax_enc;

// monotone float <-> uint encoding so min/max reduce with integer atomics
__device__ __forceinline__ unsigned fenc(float f) {
    unsigned u = __float_as_uint(f);
    return (u & 0x80000000u) ? ~u : (u | 0x80000000u);
}
__device__ __forceinline__ float fdec(unsigned e) {
    unsigned u = (e & 0x80000000u) ? (e & 0x7FFFFFFFu) : ~e;
    return __uint_as_float(u);
}

// triangular pair decode: k in [0, NPAIRS) -> (a, b) with 0 <= a <= b < NTILE
__device__ __forceinline__ int tri_off(int a) { return a * NTILE - (a * (a - 1)) / 2; }
__device__ __forceinline__ void tri_decode(int k, int& a, int& b) {
    int aa = (int)((129.0f - sqrtf(16641.0f - 8.0f * (float)k)) * 0.5f);
    aa = max(0, min(63, aa));
    while (aa < 63 && tri_off(aa + 1) <= k) aa++;
    while (aa > 0 && tri_off(aa) > k) aa--;
    a = aa;
    b = aa + (k - tri_off(aa));
}

__device__ __forceinline__ uint32_t smem_u32(const void* p) {
    uint32_t a;
    asm("{ .reg .u64 t; cvta.to.shared.u64 t, %1; cvt.u32.u64 %0, t; }" : "=r"(a) : "l"(p));
    return a;
}
__device__ __forceinline__ uint4 ldsm_x4(uint32_t addr) {
    uint4 r;
    asm volatile("ldmatrix.sync.aligned.m8n8.x4.shared.b16 {%0,%1,%2,%3}, [%4];"
                 : "=r"(r.x), "=r"(r.y), "=r"(r.z), "=r"(r.w) : "r"(addr));
    return r;
}
__device__ __forceinline__ void mma16(float* c, uint4 a, uint32_t b0, uint32_t b1) {
    asm volatile(
        "mma.sync.aligned.m16n8k16.row.col.f32.f16.f16.f32 "
        "{%0,%1,%2,%3}, {%4,%5,%6,%7}, {%8,%9}, {%0,%1,%2,%3};"
        : "+f"(c[0]), "+f"(c[1]), "+f"(c[2]), "+f"(c[3])
        : "r"(a.x), "r"(a.y), "r"(a.z), "r"(a.w), "r"(b0), "r"(b1));
}
__device__ __forceinline__ float ex2f(float x) {
    float y;
    asm("ex2.approx.f32 %0, %1;" : "=f"(y) : "f"(x));
    return y;
}
__device__ __forceinline__ float sqrtaf(float x) {
    float y;
    asm("sqrt.approx.f32 %0, %1;" : "=f"(y) : "f"(x));
    return y;
}
__device__ __forceinline__ uint4 ldg_nc4(const void* p) {
    uint4 r;
    asm volatile("ld.global.nc.v4.u32 {%0,%1,%2,%3}, [%4];"
                 : "=r"(r.x), "=r"(r.y), "=r"(r.z), "=r"(r.w) : "l"(p));
    return r;
}
#define CP_ASYNC16(dst, src) \
    asm volatile("cp.async.cg.shared.global [%0], [%1], 16;" :: "r"(dst), "l"(src))
#define CP_COMMIT() asm volatile("cp.async.commit_group;" ::: "memory")
#define CP_WAIT(n)  asm volatile("cp.async.wait_group %0;" :: "n"(n) : "memory")

// ---------------- gram smem layout (bytes): 3 stages x 32KB + sq arrays ----------------
#define OFF_SQI   98304
#define OFF_SQJ   98816
#define SM_BYTES  99328

// copy one 128-row x 64-half tile into SW128-swizzled smem via cp.async
__device__ __forceinline__ void cpasync_tile(const __half* __restrict__ src, int ldh, int k0,
                                             uint32_t smem_dst, int tid) {
    #pragma unroll
    for (int it = 0; it < 4; it++) {
        int e = tid + 256 * it;                  // 0..1023 granules of 16B
        int row = e >> 3, gq = e & 7;
        const __half* g = src + (size_t)row * ldh + k0 + gq * 8;
        uint32_t bo = (uint32_t)(row * 128 + gq * 16);
        uint32_t dst = smem_dst + (bo ^ ((bo >> 3) & 0x70));
        CP_ASYNC16(dst, g);
    }
}

__device__ __forceinline__ unsigned pack_se(unsigned simlo16, float e) {
    unsigned eh = (unsigned)__half_as_ushort(__float2half_rn(e));
    return (simlo16 & 0xFFFFu) | (eh << 16);
}

// ---------------- kernel 1: per-row prep (absorbs init; warp-per-row, no block syncs) ----------------
__global__ __launch_bounds__(256) void rowprep_kernel(const float* __restrict__ outputs,
                                                      const float* __restrict__ labels) {
    if (blockIdx.x == 0 && threadIdx.x == 0) {
        g_smin_enc = fenc(3.4e38f);
        g_smax_enc = fenc(-3.4e38f);
        g_emax_enc = fenc(0.0f);
    }

    const int row = blockIdx.x * 8 + (threadIdx.x >> 5);
    const int lane = threadIdx.x & 31;

    // labels: 4 elements per lane
    float l[4];
    float lsum = 0.0f;
    #pragma unroll
    for (int x = 0; x < 4; x++) {
        l[x] = labels[(size_t)row * CDIM + lane + 32 * x];
        lsum += l[x] * l[x];
    }
    #pragma unroll
    for (int off = 16; off; off >>= 1) lsum += __shfl_xor_sync(0xffffffffu, lsum, off);
    float invn = 1.0f / (sqrtf(lsum) + 1e-12f);
    #pragma unroll
    for (int x = 0; x < 4; x++)
        g_lab_h[(size_t)row * CDIM + lane + 32 * x] = __float2half(l[x] * invn);

    // outputs: 8 elements per lane; sq from rounded values
    float osum = 0.0f;
    #pragma unroll
    for (int x = 0; x < 8; x++) {
        float o = outputs[(size_t)row * DDIM + lane + 32 * x];
        __half h = __float2half(o);
        g_out_h[(size_t)row * DDIM + lane + 32 * x] = h;
        float f = __half2float(h);
        osum += f * f;
    }
    #pragma unroll
    for (int off = 16; off; off >>= 1) osum += __shfl_xor_sync(0xffffffffu, osum, off);
    if (lane == 0) g_sq[row] = osum;
}

// ---------------- kernel 2: fp16 mma fused grams, race-free 3-stage pipeline ----------------
__global__ __launch_bounds__(256, 2) void gram_mma() {
    int bi, bj;
    tri_decode(blockIdx.x, bi, bj);
    extern __shared__ float sm[];
    const uint32_t sb = smem_u32(sm);
    float* s_sqi = (float*)((char*)sm + OFF_SQI);
    float* s_sqj = (float*)((char*)sm + OFF_SQJ);

    const int tid = threadIdx.x;
    const int wid = tid >> 5, lane = tid & 31;
    const int warp_m = wid >> 2, warp_n = wid & 3;
    const int g = lane >> 2, tig = lane & 3;
    const int i0 = bi * TILE, j0 = bj * TILE;

    if (tid < 128) {
        s_sqi[tid] = g_sq[i0 + tid];
        s_sqj[tid] = g_sq[j0 + tid];
    }

    // ldmatrix per-lane address precompute (byte offsets within 128x64h tile, 128B rows)
    const int laneA_row = lane & 15;
    const uint32_t baseA = (uint32_t)(((warp_m * 64 + laneA_row) << 7) + ((lane >> 4) << 4));
    const uint32_t xorA = (uint32_t)((laneA_row & 7) << 4);
    const int rowB = warp_n * 32 + ((lane >> 4) << 3) + (lane & 7);
    const uint32_t baseB = (uint32_t)((rowB << 7) + (((lane >> 3) & 1) << 4));
    const uint32_t xorB = (uint32_t)((rowB & 7) << 4);

    float c[4][4][4];
    #pragma unroll
    for (int mf = 0; mf < 4; mf++)
        #pragma unroll
        for (int nf = 0; nf < 4; nf++)
            #pragma unroll
            for (int r = 0; r < 4; r++) c[mf][nf][r] = 0.0f;

    unsigned simh[32];   // register-resident sim tile (fp16x2)

    const __half* AiL = g_lab_h + (size_t)i0 * CDIM;
    const __half* BjL = g_lab_h + (size_t)j0 * CDIM;
    const __half* AiO = g_out_h + (size_t)i0 * DDIM;
    const __half* BjO = g_out_h + (size_t)j0 * DDIM;

    // preload chunks 0 and 1 (separate commit groups)
    cpasync_tile(AiL, CDIM, 0, sb, tid);
    cpasync_tile(BjL, CDIM, 0, sb + 16384, tid);
    CP_COMMIT();
    cpasync_tile(AiL, CDIM, 64, sb + 32768, tid);
    cpasync_tile(BjL, CDIM, 64, sb + 32768 + 16384, tid);
    CP_COMMIT();

    // merged 6-chunk pipeline: chunks 0-1 = label gram, 2-5 = output gram
    // order per iteration: WAIT(ch) -> sync -> prefetch(ch+2) -> compute(ch)
    #pragma unroll 1
    for (int ch = 0; ch < 6; ch++) {
        if (ch < 5) CP_WAIT(1);
        else        CP_WAIT(0);
        __syncthreads();

        if (ch + 2 < 6) {
            int nx = ch + 2;
            uint32_t nb = sb + (nx % 3) * 32768;
            if (nx < 2) {
                cpasync_tile(AiL, CDIM, nx * 64, nb, tid);
                cpasync_tile(BjL, CDIM, nx * 64, nb + 16384, tid);
            } else {
                cpasync_tile(AiO, DDIM, (nx - 2) * 64, nb, tid);
                cpasync_tile(BjO, DDIM, (nx - 2) * 64, nb + 16384, tid);
            }
            CP_COMMIT();
        }

        uint32_t sA = sb + (ch % 3) * 32768;
        uint32_t sB = sA + 16384;
        #pragma unroll
        for (int ks = 0; ks < 4; ks++) {
            uint4 a[4];
            #pragma unroll
            for (int mf = 0; mf < 4; mf++)
                a[mf] = ldsm_x4(sA + ((baseA + mf * 2048 + ks * 32) ^ xorA));
            uint4 b0 = ldsm_x4(sB + ((baseB + ks * 32) ^ xorB));
            uint4 b1 = ldsm_x4(sB + ((baseB + 2048 + ks * 32) ^ xorB));
            #pragma unroll
            for (int mf = 0; mf < 4; mf++) {
                mma16(c[mf][0], a[mf], b0.x, b0.y);
                mma16(c[mf][1], a[mf], b0.z, b0.w);
                mma16(c[mf][2], a[mf], b1.x, b1.y);
                mma16(c[mf][3], a[mf], b1.z, b1.w);
            }
        }
        if (ch == 1) {
            // epilogue A (overlaps in-flight copies): pack sim to regs, min/max, zero accums
            float lmin = 3.4e38f, lmax = -3.4e38f;
            #pragma unroll
            for (int mf = 0; mf < 4; mf++) {
                #pragma unroll
                for (int nf = 0; nf < 4; nf++) {
                    float v0 = c[mf][nf][0], v1 = c[mf][nf][1];
                    float v2 = c[mf][nf][2], v3 = c[mf][nf][3];
                    lmin = fminf(lmin, fminf(fminf(v0, v1), fminf(v2, v3)));
                    lmax = fmaxf(lmax, fmaxf(fmaxf(v0, v1), fmaxf(v2, v3)));
                    int idx0 = (mf * 4 + nf) * 2;
                    __half2 h01 = __floats2half2_rn(v0, v1);
                    __half2 h23 = __floats2half2_rn(v2, v3);
                    simh[idx0]     = *(unsigned*)&h01;
                    simh[idx0 + 1] = *(unsigned*)&h23;
                    c[mf][nf][0] = 0.0f; c[mf][nf][1] = 0.0f;
                    c[mf][nf][2] = 0.0f; c[mf][nf][3] = 0.0f;
                }
            }
            #pragma unroll
            for (int off = 16; off; off >>= 1) {
                lmin = fminf(lmin, __shfl_xor_sync(0xffffffffu, lmin, off));
                lmax = fmaxf(lmax, __shfl_xor_sync(0xffffffffu, lmax, off));
            }
            if (lane == 0) {
                atomicMin(&g_smin_enc, fenc(lmin));
                atomicMax(&g_smax_enc, fenc(lmax));
            }
        }
    }

    // epilogue B: eud + packed (sim|eud) store, upper tile only
    {
        float lemax = 0.0f;
        #pragma unroll
        for (int mf = 0; mf < 4; mf++) {
            int il = warp_m * 64 + mf * 16 + g;
            float q0 = s_sqi[il], q1 = s_sqi[il + 8];
            #pragma unroll
            for (int nf = 0; nf < 4; nf++) {
                int jl = warp_n * 32 + nf * 8 + 2 * tig;
                float r0 = s_sqj[jl], r1 = s_sqj[jl + 1];
                float d0 = q0 + r0 - 2.0f * c[mf][nf][0];
                float d1 = q0 + r1 - 2.0f * c[mf][nf][1];
                float d2_ = q1 + r0 - 2.0f * c[mf][nf][2];
                float d3 = q1 + r1 - 2.0f * c[mf][nf][3];
                float v0 = (d0 > 0.0f) ? sqrtaf(d0) : 0.0f;
                float v1 = (d1 > 0.0f) ? sqrtaf(d1) : 0.0f;
                float v2 = (d2_ > 0.0f) ? sqrtaf(d2_) : 0.0f;
                float v3 = (d3 > 0.0f) ? sqrtaf(d3) : 0.0f;
                if (i0 + il == j0 + jl) v0 = 0.0f;
                if (i0 + il == j0 + jl + 1) v1 = 0.0f;
                if (i0 + il + 8 == j0 + jl) v2 = 0.0f;
                if (i0 + il + 8 == j0 + jl + 1) v3 = 0.0f;
                lemax = fmaxf(lemax, fmaxf(fmaxf(v0, v1), fmaxf(v2, v3)));

                int idx0 = (mf * 4 + nf) * 2;
                unsigned sp01 = simh[idx0];
                unsigned sp23 = simh[idx0 + 1];
                unsigned u0 = pack_se(sp01, v0);
                unsigned u1 = pack_se(sp01 >> 16, v1);
                unsigned u2 = pack_se(sp23, v2);
                unsigned u3 = pack_se(sp23 >> 16, v3);

                *(uint2*)&g_se[(size_t)(i0 + il) * BSZ + j0 + jl]     = make_uint2(u0, u1);
                *(uint2*)&g_se[(size_t)(i0 + il + 8) * BSZ + j0 + jl] = make_uint2(u2, u3);
            }
        }
        #pragma unroll
        for (int off = 16; off; off >>= 1)
            lemax = fmaxf(lemax, __shfl_xor_sync(0xffffffffu, lemax, off));
        if (lane == 0) atomicMax(&g_emax_enc, fenc(lemax));
    }
}

// ---------------- kernel 3: tile loss — batched shfl reductions, prefetched loads ----------------
__global__ __launch_bounds__(256, 4) void loss_tile_kernel() {
    int bi, bj;
    tri_decode((int)blockIdx.x, bi, bj);
    const int i0 = bi * TILE, j0 = bj * TILE;
    const int t = threadIdx.x;
    const int w = t >> 5, lane = t & 31;
    const int cg = lane & 15;        // 8-column group: cols cg*8 .. cg*8+7
    const int rhalf = lane >> 4;     // row within the pair

    const float L2E = 1.4426950408889634f;
    const float smin = fdec(g_smin_enc);
    const float smax = fdec(g_smax_enc);
    const float emax = fdec(g_emax_enc);
    const float c1 = L2E / (smax - smin);
    const float c0 = -smin * c1;
    const float c2 = L2E / emax;
    const float sthr = smin + 0.5f * (smax - smin);

    __shared__ float2 scol[8][128];

    float cp[8] = {0, 0, 0, 0, 0, 0, 0, 0};
    float cn[8] = {0, 0, 0, 0, 0, 0, 0, 0};
    float rp[8], rn[8];

    const char* base0 = (const char*)&g_se[(size_t)(i0 + w * 16 + rhalf) * BSZ + j0 + cg * 8];
    const size_t rstep = (size_t)2 * BSZ * 4;   // 2 rows per iteration, 4B per element

    uint4 v0 = ldg_nc4(base0);
    uint4 v1 = ldg_nc4(base0 + 16);

    #pragma unroll
    for (int it = 0; it < 8; it++) {
        uint4 a0 = v0, a1 = v1;
        if (it < 7) {
            const char* nb = base0 + (size_t)(it + 1) * rstep;
            v0 = ldg_nc4(nb);
            v1 = ldg_nc4(nb + 16);
        }
        unsigned uu[8] = {a0.x, a0.y, a0.z, a0.w, a1.x, a1.y, a1.z, a1.w};
        float p = 0.0f, n = 0.0f;
        #pragma unroll
        for (int x = 0; x < 8; x++) {
            float2 f = __half22float2(*(__half2*)&uu[x]);   // f.x = sim, f.y = eud
            float d = fmaf(f.y, c2, fmaf(f.x, c1, c0));
            bool pos = f.x > sthr;
            float val = ex2f(pos ? d : (L2E - d));
            float vp = pos ? val : 0.0f;
            float vn = pos ? 0.0f : val;
            p += vp; n += vn;
            cp[x] += vp; cn[x] += vn;
        }
        rp[it] = p;
        rn[it] = n;
    }

    // batched row reductions: 16 independent shfl chains pipeline through the unit
    #pragma unroll
    for (int off = 8; off; off >>= 1) {
        #pragma unroll
        for (int it = 0; it < 8; it++) {
            rp[it] += __shfl_xor_sync(0xffffffffu, rp[it], off);
            rn[it] += __shfl_xor_sync(0xffffffffu, rn[it], off);
        }
    }
    if (cg == 0) {
        #pragma unroll
        for (int it = 0; it < 8; it++) {
            int row = w * 16 + it * 2 + rhalf;
            g_part[(size_t)bj * BSZ + i0 + row] = make_float2(rp[it], rn[it]);
        }
    }

    // fold the two row-halves' column partials, then cross-warp reduce in smem
    #pragma unroll
    for (int x = 0; x < 8; x++) {
        cp[x] += __shfl_xor_sync(0xffffffffu, cp[x], 16);
        cn[x] += __shfl_xor_sync(0xffffffffu, cn[x], 16);
    }
    if (rhalf == 0) {
        #pragma unroll
        for (int x = 0; x < 8; x++) scol[w][cg * 8 + x] = make_float2(cp[x], cn[x]);
    }
    __syncthreads();
    if (bi != bj && t < 128) {
        float p = 0.0f, n = 0.0f;
        #pragma unroll
        for (int ww = 0; ww < 8; ww++) {
            float2 v = scol[ww][t];
            p += v.x; n += v.y;
        }
        g_part[(size_t)bi * BSZ + j0 + t] = make_float2(p, n);
    }
}

// ---------------- kernel 4: per-row reduce — 8 warps per 32 rows, coalesced ----------------
__global__ __launch_bounds__(256) void rowreduce_kernel() {
    const int w = threadIdx.x >> 5, lane = threadIdx.x & 31;
    const int row = blockIdx.x * 32 + lane;

    // warp w sums tiles w*8 .. w*8+7 for 32 consecutive rows (coalesced, MLP-8)
    float2 v[8];
    #pragma unroll
    for (int k = 0; k < 8; k++)
        v[k] = g_part[(size_t)(w * 8 + k) * BSZ + row];
    float P = 0.0f, N = 0.0f;
    #pragma unroll
    for (int k = 0; k < 8; k++) { P += v[k].x; N += v[k].y; }

    __shared__ float2 sc[8][32];
    sc[w][lane] = make_float2(P, N);
    __syncthreads();
    if (w == 0) {
        float Pt = 0.0f, Nt = 0.0f;
        #pragma unroll
        for (int ww = 0; ww < 8; ww++) {
            float2 u = sc[ww][lane];
            Pt += u.x; Nt += u.y;
        }
        float lp = fmaxf(logf(Pt), 0.0f);   // log(0) = -inf -> clamped to 0
        float ln = fmaxf(logf(Nt), 0.0f);
        g_rowloss[row] = lp + ln;
    }
}

// ---------------- kernel 5: deterministic final mean ----------------
__global__ __launch_bounds__(256) void final_kernel(float* __restrict__ out) {
    __shared__ float s[256];
    const int t = threadIdx.x;
    float a = 0.0f;
    for (int i = t; i < BSZ; i += 256) a += g_rowloss[i];
    s[t] = a;
    __syncthreads();
    #pragma unroll
    for (int o = 128; o; o >>= 1) {
        if (t < o) s[t] += s[t + o];
        __syncthreads();
    }
    if (t == 0) out[0] = s[0] * (1.0f / (float)BSZ);
}

// ---------------- launch ----------------
extern "C" void kernel_launch(void* const* d_in, const int* in_sizes, int n_in,
                              void* d_out, int out_size) {
    const float* outputs = (const float*)d_in[0];
    const float* labels  = (const float*)d_in[1];
    if (n_in >= 2 && in_sizes[0] == BSZ * CDIM && in_sizes[1] == BSZ * DDIM) {
        const float* tmp = outputs; outputs = labels; labels = tmp;
    }
    float* out = (float*)d_out;

    cudaFuncSetAttribute(gram_mma, cudaFuncAttributeMaxDynamicSharedMemorySize, SM_BYTES);

    rowprep_kernel<<<BSZ / 8, 256>>>(outputs, labels);
    gram_mma<<<NPAIRS, 256, SM_BYTES>>>();
    loss_tile_kernel<<<NPAIRS, 256>>>();
    rowreduce_kernel<<<BSZ / 32, 256>>>();
    final_kernel<<<1, 256>>>(out);
}